// round 14
// baseline (speedup 1.0000x reference)
#include <cuda_runtime.h>
#include <cuda_fp16.h>
#include <math.h>
#include <stdint.h>

// ---------------- problem constants (fixed shapes) ----------------
#define BB   8
#define TT   2048
#define CC   1024
#define RR   64
#define ARR  32
#define FFD  4096
#define MM   (BB*TT)        // 16384 rows
#define SEG  128
#define LSEG (TT/SEG)       // 16
#define BC   (BB*CC)        // 8192 channels

typedef __half f16;

// ---------------- side stream (created at load, NOT in kernel_launch) ---
struct SideStream {
    cudaStream_t s = 0;
    cudaEvent_t ev[6] = {};
    bool ok = false;
    SideStream() {
        ok = (cudaStreamCreateWithFlags(&s, cudaStreamNonBlocking) == cudaSuccess);
        for (int i = 0; i < 6 && ok; i++)
            ok = (cudaEventCreateWithFlags(&ev[i], cudaEventDisableTiming) == cudaSuccess);
    }
};
static SideStream g_ss;   // constructed before harness checkpoints

// ---------------- scratch (static device globals; no allocs) ------
__device__ __align__(256) float g_x1[MM*CC];
__device__ __align__(256) float g_x2[MM*CC];
__device__ __align__(256) float g_hloc[SEG*BC];
__device__ __align__(256) float g_hin [SEG*BC];

// fp16 activation buffers
__device__ __align__(256) f16 g_mix_h[MM*CC];
__device__ __align__(256) f16 g_qkvr_h[MM*3*RR];                 // [M,192] q|k|v
__device__ __align__(256) f16 g_qkv[(size_t)3*MM*CC];            // q,k,v fp16
__device__ __align__(256) f16 g_ys_h[MM*CC];
__device__ __align__(256) f16 g_h2_h[MM*CC];
__device__ __align__(256) f16 g_ff_h[(size_t)MM*FFD];
__device__ __align__(256) f16 g_x2h[MM*CC];
__device__ __align__(256) f16 g_ad_h[MM*64];                     // K padded 32->64

// fp16 transposed weights ([N,K] K-major)
__device__ __align__(256) f16 g_uT_h[3*RR*CC];                   // qu|ku|vu [192,1024]
__device__ __align__(256) f16 g_vT_h[3*CC*RR];                   // qv|kv|vv 3x[1024,64]
__device__ __align__(256) f16 g_owT_h[CC*CC];
__device__ __align__(256) f16 g_w1T_h[(size_t)FFD*CC];
__device__ __align__(256) f16 g_w2T_h[(size_t)CC*FFD];
__device__ __align__(256) f16 g_adwT_h[ARR*CC];
__device__ __align__(256) f16 g_auwT_h[CC*64];                   // K padded 32->64

// ---------------- PTX helpers ---------------------------------------
__device__ __forceinline__ uint32_t smem_u32(const void* p) {
    uint32_t a;
    asm("{ .reg .u64 t; cvta.to.shared.u64 t, %1; cvt.u32.u64 %0, t; }" : "=r"(a) : "l"(p));
    return a;
}
#define SWZ128(b) ((b) ^ (((b) >> 3) & 0x70))

__device__ __forceinline__ void cp16(uint32_t dst, const void* src) {
    asm volatile("cp.async.cg.shared.global [%0], [%1], 16;" :: "r"(dst), "l"(src));
}
#define CP_COMMIT()  asm volatile("cp.async.commit_group;" ::: "memory")

__device__ __forceinline__ void ldsm_x4(uint32_t* r, uint32_t addr) {
    asm volatile("ldmatrix.sync.aligned.m8n8.x4.shared.b16 {%0,%1,%2,%3}, [%4];"
                 : "=r"(r[0]), "=r"(r[1]), "=r"(r[2]), "=r"(r[3]) : "r"(addr));
}
__device__ __forceinline__ void mma16816(float* d, const uint32_t* a, const uint32_t* b) {
    asm volatile("mma.sync.aligned.m16n8k16.row.col.f32.f16.f16.f32 "
                 "{%0,%1,%2,%3}, {%4,%5,%6,%7}, {%8,%9}, {%0,%1,%2,%3};"
                 : "+f"(d[0]), "+f"(d[1]), "+f"(d[2]), "+f"(d[3])
                 : "r"(a[0]), "r"(a[1]), "r"(a[2]), "r"(a[3]), "r"(b[0]), "r"(b[1]));
}
__device__ __forceinline__ float tanh_fast(float x) {
    float y;
    asm("tanh.approx.f32 %0, %1;" : "=f"(y) : "f"(x));
    return y;
}

// ---------------- misc helpers --------------------------------------
__device__ __forceinline__ float gelu_tanh(float x) {
    float x3 = x * x * x;
    return 0.5f * x * (1.f + tanh_fast(0.7978845608028654f * (x + 0.044715f * x3)));
}
__device__ __forceinline__ float sigmoid_fast(float x) {
    return 0.5f + 0.5f * tanh_fast(0.5f * x);
}
__device__ __forceinline__ float block_sum_256(float val, float* sh) {
    int lane = threadIdx.x & 31;
#pragma unroll
    for (int o = 16; o > 0; o >>= 1) val += __shfl_xor_sync(0xffffffffu, val, o);
    if (lane == 0) sh[threadIdx.x >> 5] = val;
    __syncthreads();
    float r = (lane < 8) ? sh[lane] : 0.f;
#pragma unroll
    for (int o = 4; o > 0; o >>= 1) r += __shfl_xor_sync(0xffffffffu, r, o);
    r = __shfl_sync(0xffffffffu, r, 0);
    __syncthreads();
    return r;
}

// double-LN of one row's float4 slice (two chained LayerNorms)
__device__ __forceinline__ float4 ln2x(float4 v,
                                       const float* __restrict__ g1, const float* __restrict__ b1,
                                       const float* __restrict__ g2, const float* __restrict__ b2,
                                       int tid, float* sh)
{
#pragma unroll
    for (int pass = 0; pass < 2; pass++) {
        const float* gg = pass ? g2 : g1;
        const float* bb = pass ? b2 : b1;
        float mean = block_sum_256(v.x + v.y + v.z + v.w, sh) * (1.f / CC);
        float dx = v.x - mean, dy = v.y - mean, dz = v.z - mean, dw = v.w - mean;
        float var = block_sum_256(dx*dx + dy*dy + dz*dz + dw*dw, sh) * (1.f / CC);
        float rstd = rsqrtf(var + 1e-5f);
        float4 gv = *(const float4*)(gg + tid * 4);
        float4 bv = *(const float4*)(bb + tid * 4);
        v.x = dx * rstd * gv.x + bv.x;
        v.y = dy * rstd * gv.y + bv.y;
        v.z = dz * rstd * gv.z + bv.z;
        v.w = dw * rstd * gv.w + bv.w;
    }
    return v;
}

// ---------------- fused LN1(LN1(x)) + token-shift mix -> fp16 --------
__global__ void ln1_mix_kernel(const float* __restrict__ x,
                               const float* __restrict__ g1, const float* __restrict__ b1,
                               const float* __restrict__ g2, const float* __restrict__ b2,
                               f16* __restrict__ mh)
{
    __shared__ float sh[8];
    int row = blockIdx.x;
    int tid = threadIdx.x;
    int t = row & (TT - 1);
    float4 vc = *(const float4*)(x + (size_t)row * CC + tid * 4);
    vc = ln2x(vc, g1, b1, g2, b2, tid, sh);
    float4 vp = make_float4(0.f, 0.f, 0.f, 0.f);
    if (t > 0) {   // uniform across block
        vp = *(const float4*)(x + (size_t)(row - 1) * CC + tid * 4);
        vp = ln2x(vp, g1, b1, g2, b2, tid, sh);
    }
    __half2 h01 = __floats2half2_rn(0.5f * (vc.x + vp.x), 0.5f * (vc.y + vp.y));
    __half2 h23 = __floats2half2_rn(0.5f * (vc.z + vp.z), 0.5f * (vc.w + vp.w));
    uint2 u; u.x = *(uint32_t*)&h01; u.y = *(uint32_t*)&h23;
    *(uint2*)(mh + (size_t)row * CC + tid * 4) = u;
}

// ---------------- LayerNorm (single, fp16 out) -----------------------
__global__ void ln_kernel(const float* __restrict__ x,
                          const float* __restrict__ g1, const float* __restrict__ b1,
                          f16* __restrict__ oh)
{
    __shared__ float sh[8];
    int row = blockIdx.x;
    int tid = threadIdx.x;
    float4 v = *(const float4*)(x + (size_t)row * CC + tid * 4);
    float mean = block_sum_256(v.x + v.y + v.z + v.w, sh) * (1.f / CC);
    float dx = v.x - mean, dy = v.y - mean, dz = v.z - mean, dw = v.w - mean;
    float var = block_sum_256(dx*dx + dy*dy + dz*dz + dw*dw, sh) * (1.f / CC);
    float rstd = rsqrtf(var + 1e-5f);
    float4 gv = *(const float4*)(g1 + tid * 4);
    float4 bv = *(const float4*)(b1 + tid * 4);
    __half2 h01 = __floats2half2_rn(dx * rstd * gv.x + bv.x, dy * rstd * gv.y + bv.y);
    __half2 h23 = __floats2half2_rn(dz * rstd * gv.z + bv.z, dw * rstd * gv.w + bv.w);
    uint2 u; u.x = *(uint32_t*)&h01; u.y = *(uint32_t*)&h23;
    *(uint2*)(oh + (size_t)row * CC + tid * 4) = u;
}

// ---------------- weight transpose (fp16 hi only) ---------------------
__global__ void transpose_split(const float* __restrict__ w, int R, int S, int ldout,
                                f16* __restrict__ th)
{
    __shared__ float t[32][33];
    int s0 = blockIdx.x * 32, r0 = blockIdx.y * 32;
    int tx = threadIdx.x, ty = threadIdx.y;   // (16,16)
#pragma unroll
    for (int i = ty; i < 32; i += 16) {
        float2 v = make_float2(0.f, 0.f);
        if (r0 + i < R) v = *(const float2*)(w + (size_t)(r0 + i) * S + s0 + tx * 2);
        t[i][tx*2] = v.x; t[i][tx*2+1] = v.y;
    }
    __syncthreads();
#pragma unroll
    for (int i = ty; i < 32; i += 16) {
        float a = t[tx*2][i], b = t[tx*2+1][i];
        size_t o = (size_t)(s0 + i) * ldout + r0 + tx * 2;
        __half2 hh = __floats2half2_rn(a, b);
        *(__half2*)(th + o) = hh;
    }
}

__global__ void transpose_split3(const float* __restrict__ w0, const float* __restrict__ w1,
                                 const float* __restrict__ w2,
                                 int R, int S, int ldout, size_t zoff,
                                 f16* __restrict__ th)
{
    __shared__ float t[32][33];
    const float* w = (blockIdx.z == 0) ? w0 : (blockIdx.z == 1) ? w1 : w2;
    th += blockIdx.z * zoff;
    int s0 = blockIdx.x * 32, r0 = blockIdx.y * 32;
    int tx = threadIdx.x, ty = threadIdx.y;
#pragma unroll
    for (int i = ty; i < 32; i += 16) {
        float2 v = make_float2(0.f, 0.f);
        if (r0 + i < R) v = *(const float2*)(w + (size_t)(r0 + i) * S + s0 + tx * 2);
        t[i][tx*2] = v.x; t[i][tx*2+1] = v.y;
    }
    __syncthreads();
#pragma unroll
    for (int i = ty; i < 32; i += 16) {
        float a = t[tx*2][i], b = t[tx*2+1][i];
        size_t o = (size_t)(s0 + i) * ldout + r0 + tx * 2;
        __half2 hh = __floats2half2_rn(a, b);
        *(__half2*)(th + o) = hh;
    }
}

// ---------------- HMMA fp16 GEMM (R8-proven shapes, 1-pass) -----------
template<int BN, int WMS, int WNS, int S,
         bool BIAS, bool GELU, bool RES, bool OUTF32, bool OUTH>
__global__ void __launch_bounds__(256, 2)
mm_h(int M, int N, int K, int lda, int ldh,
     size_t az, size_t bz, size_t czf, size_t czh,
     const f16* __restrict__ Ah, const f16* __restrict__ Bh,
     float* __restrict__ C, f16* __restrict__ Ch,
     const float* __restrict__ bias, const float* __restrict__ res)
{
    constexpr int BM = 128;
    constexpr int NTH = 256;
    constexpr int TMW = BM / WMS;
    constexpr int TNW = BN / WNS;
    constexpr int MT = TMW / 16;
    constexpr int NT = TNW / 8;
    constexpr int A_BYTES = BM * 128;
    constexpr int B_BYTES = BN * 128;
    constexpr int STAGE   = A_BYTES + B_BYTES;

    extern __shared__ char smem[];
    const uint32_t sb = smem_u32(smem);

    const int z = blockIdx.z;
    Ah += (size_t)z * az;
    Bh += (size_t)z * bz;
    if (OUTF32) C  += (size_t)z * czf;
    if (OUTH)   Ch += (size_t)z * czh;

    const int tid  = threadIdx.x;
    const int lane = tid & 31;
    const int warp = tid >> 5;
    const int wm   = warp / WNS;
    const int wn   = warp % WNS;
    const int brow = blockIdx.y * BM;
    const int bcol = blockIdx.x * BN;
    const int NK   = K >> 6;

    float acc[MT][NT][4];
#pragma unroll
    for (int i = 0; i < MT; i++)
#pragma unroll
        for (int j = 0; j < NT; j++)
#pragma unroll
            for (int e = 0; e < 4; e++) acc[i][j][e] = 0.f;

    auto load_stage = [&](int kc, int s) {
        uint32_t base = sb + s * STAGE;
#pragma unroll 2
        for (int i = tid; i < BM * 8; i += NTH) {
            int r = i >> 3, j = i & 7;
            size_t go = (size_t)(brow + r) * lda + (size_t)kc * 64 + j * 8;
            uint32_t sw = SWZ128((uint32_t)(r * 128 + j * 16));
            cp16(base + sw, Ah + go);
        }
#pragma unroll 2
        for (int i = tid; i < BN * 8; i += NTH) {
            int r = i >> 3, j = i & 7;
            size_t go = (size_t)(bcol + r) * K + (size_t)kc * 64 + j * 8;
            uint32_t sw = SWZ128((uint32_t)(r * 128 + j * 16));
            cp16(base + A_BYTES + sw, Bh + go);
        }
        CP_COMMIT();
    };

    const int npre = (S - 1 < NK) ? S - 1 : NK;
    for (int i = 0; i < npre; i++) load_stage(i, i);
    for (int i = npre; i < S - 1; i++) CP_COMMIT();

    for (int kc = 0; kc < NK; kc++) {
        asm volatile("cp.async.wait_group %0;" :: "n"(S - 2) : "memory");
        __syncthreads();
        if (kc + S - 1 < NK) load_stage(kc + S - 1, (kc + S - 1) % S);
        else                 CP_COMMIT();

        const uint32_t st = sb + (kc % S) * STAGE;
#pragma unroll
        for (int ks = 0; ks < 4; ks++) {
            uint32_t a_h[MT][4];
#pragma unroll
            for (int mt = 0; mt < MT; mt++) {
                int r = wm * TMW + mt * 16 + (lane & 15);
                uint32_t off = SWZ128((uint32_t)(r * 128 + ks * 32 + ((lane >> 4) << 4)));
                ldsm_x4(a_h[mt], st + off);
            }
            uint32_t b_h[NT][2];
#pragma unroll
            for (int p = 0; p < NT / 2; p++) {
                int r = wn * TNW + p * 16 + (lane & 7) + ((lane >> 4) << 3);
                uint32_t off = SWZ128((uint32_t)(r * 128 + ks * 32 + (((lane >> 3) & 1) << 4)));
                uint32_t t4[4];
                ldsm_x4(t4, st + A_BYTES + off);
                b_h[2*p][0] = t4[0]; b_h[2*p][1] = t4[1];
                b_h[2*p+1][0] = t4[2]; b_h[2*p+1][1] = t4[3];
            }
#pragma unroll
            for (int mt = 0; mt < MT; mt++)
#pragma unroll
                for (int nt = 0; nt < NT; nt++) mma16816(acc[mt][nt], a_h[mt], b_h[nt]);
        }
    }

    // ---- epilogue ----
#pragma unroll
    for (int mt = 0; mt < MT; mt++) {
#pragma unroll
        for (int nt = 0; nt < NT; nt++) {
            int r0 = brow + wm * TMW + mt * 16 + (lane >> 2);
            int cg = bcol + wn * TNW + nt * 8 + ((lane & 3) << 1);
#pragma unroll
            for (int h = 0; h < 2; h++) {
                int r = r0 + h * 8;
                float v0 = acc[mt][nt][2*h], v1 = acc[mt][nt][2*h+1];
                if (BIAS) { v0 += bias[cg]; v1 += bias[cg + 1]; }
                if (GELU) { v0 = gelu_tanh(v0); v1 = gelu_tanh(v1); }
                if (RES) {
                    float2 rv = *(const float2*)(res + (size_t)r * N + cg);
                    v0 += rv.x; v1 += rv.y;
                }
                if (OUTF32)
                    *(float2*)(C + (size_t)r * N + cg) = make_float2(v0, v1);
                if (OUTH) {
                    __half2 hh = __floats2half2_rn(v0, v1);
                    *(__half2*)(Ch + (size_t)r * ldh + cg) = hh;
                }
            }
        }
    }
    if (OUTH && ldh > N) {
        int pads = (ldh - N) >> 3;
        for (int i = tid; i < BM * pads; i += NTH) {
            int r = brow + i / pads;
            int c = N + (i % pads) * 8;
            uint4 zv = make_uint4(0, 0, 0, 0);
            *(uint4*)(Ch + (size_t)r * ldh + c) = zv;
        }
    }
}

// ---------------- segmented scan (8 channels/thread, uint4 I/O) ------
__global__ void scan_local(const f16* __restrict__ k, const f16* __restrict__ v,
                           const float* __restrict__ td, float* __restrict__ hloc)
{
    int idx = blockIdx.x * blockDim.x + threadIdx.x;   // < SEG*BB*(CC/8)
    int c8 = idx & (CC/8 - 1);
    int rest = idx >> 7;
    int b = rest & (BB - 1);
    int seg = rest >> 3;
    int c0 = c8 * 8;
    float4 t0 = *(const float4*)(td + c0);
    float4 t1 = *(const float4*)(td + c0 + 4);
    float d[8] = {expf(-expf(t0.x)), expf(-expf(t0.y)), expf(-expf(t0.z)), expf(-expf(t0.w)),
                  expf(-expf(t1.x)), expf(-expf(t1.y)), expf(-expf(t1.z)), expf(-expf(t1.w))};
    float h[8] = {0.f,0.f,0.f,0.f,0.f,0.f,0.f,0.f};
    size_t base = ((size_t)(b * TT + seg * LSEG)) * CC + c0;
#pragma unroll 4
    for (int i = 0; i < LSEG; i++) {
        uint4 ku = *(const uint4*)(k + base);
        uint4 vu = *(const uint4*)(v + base);
        const __half2* kh = (const __half2*)&ku;
        const __half2* vh = (const __half2*)&vu;
#pragma unroll
        for (int j = 0; j < 4; j++) {
            float2 kf = __half22float2(kh[j]);
            float2 vf = __half22float2(vh[j]);
            h[2*j]   = d[2*j]   * h[2*j]   + kf.x * vf.x;
            h[2*j+1] = d[2*j+1] * h[2*j+1] + kf.y * vf.y;
        }
        base += CC;
    }
    int o = seg * BC + b * CC + c0;
    *(float4*)(hloc + o)     = make_float4(h[0], h[1], h[2], h[3]);
    *(float4*)(hloc + o + 4) = make_float4(h[4], h[5], h[6], h[7]);
}

__global__ void scan_combine(const float* __restrict__ hloc, const float* __restrict__ h0,
                             const float* __restrict__ td, float* __restrict__ hin,
                             float* __restrict__ out, long out_size)
{
    int rem = blockIdx.x * blockDim.x + threadIdx.x;   // < BC
    int c = rem & (CC - 1);
    float e = expf(td[c]);
    float dL = expf(-(float)LSEG * e);
    float h = h0[rem];
#pragma unroll
    for (int s = 0; s < SEG; s++) {
        hin[s * BC + rem] = h;
        h = dL * h + hloc[s * BC + rem];
    }
    if (out_size >= (long)MM * CC + BC)
        out[(size_t)MM * CC + rem] = h;
}

// batch-sliced apply: handles batches [b0, b0+NB), NB = 1<<bshift
__global__ void scan_apply(const f16* __restrict__ k, const f16* __restrict__ v,
                           const f16* __restrict__ q, const float* __restrict__ td,
                           const float* __restrict__ hin, f16* __restrict__ yh,
                           int b0, int bmask, int bshift)
{
    int idx = blockIdx.x * blockDim.x + threadIdx.x;
    int c8 = idx & (CC/8 - 1);
    int rest = idx >> 7;
    int b = b0 + (rest & bmask);
    int seg = rest >> bshift;
    int c0 = c8 * 8;
    float4 t0 = *(const float4*)(td + c0);
    float4 t1 = *(const float4*)(td + c0 + 4);
    float d[8] = {expf(-expf(t0.x)), expf(-expf(t0.y)), expf(-expf(t0.z)), expf(-expf(t0.w)),
                  expf(-expf(t1.x)), expf(-expf(t1.y)), expf(-expf(t1.z)), expf(-expf(t1.w))};
    int ho = seg * BC + b * CC + c0;
    float4 h03 = *(const float4*)(hin + ho);
    float4 h47 = *(const float4*)(hin + ho + 4);
    float h[8] = {h03.x, h03.y, h03.z, h03.w, h47.x, h47.y, h47.z, h47.w};
    size_t base = ((size_t)(b * TT + seg * LSEG)) * CC + c0;
#pragma unroll 4
    for (int i = 0; i < LSEG; i++) {
        uint4 ku = *(const uint4*)(k + base);
        uint4 vu = *(const uint4*)(v + base);
        uint4 qu = *(const uint4*)(q + base);
        const __half2* kh = (const __half2*)&ku;
        const __half2* vh = (const __half2*)&vu;
        const __half2* qh = (const __half2*)&qu;
        uint4 yo;
        uint32_t* yp = (uint32_t*)&yo;
#pragma unroll
        for (int j = 0; j < 4; j++) {
            float2 kf = __half22float2(kh[j]);
            float2 vf = __half22float2(vh[j]);
            float2 qf = __half22float2(qh[j]);
            h[2*j]   = d[2*j]   * h[2*j]   + kf.x * vf.x;
            h[2*j+1] = d[2*j+1] * h[2*j+1] + kf.y * vf.y;
            __half2 yv = __floats2half2_rn(h[2*j]   * sigmoid_fast(qf.x),
                                           h[2*j+1] * sigmoid_fast(qf.y));
            yp[j] = *(uint32_t*)&yv;
        }
        *(uint4*)(yh + base) = yo;
        base += CC;
    }
}

// ---------------- launch ----------------------------------------------
#define SMEMSZ(BN, S) ((S) * ((128 + (BN)) * 128))

extern "C" void kernel_launch(void* const* d_in, const int* in_sizes, int n_in,
                              void* d_out, int out_size)
{
    const float* x     = (const float*)d_in[0];
    const float* h0    = (const float*)d_in[1];
    const float* ln1_g = (const float*)d_in[2];
    const float* ln1_b = (const float*)d_in[3];
    const float* tm_g  = (const float*)d_in[4];
    const float* tm_b  = (const float*)d_in[5];
    const float* qu    = (const float*)d_in[6];
    const float* qv    = (const float*)d_in[7];
    const float* ku    = (const float*)d_in[8];
    const float* kvw   = (const float*)d_in[9];
    const float* vu    = (const float*)d_in[10];
    const float* vvw   = (const float*)d_in[11];
    const float* td    = (const float*)d_in[12];
    const float* out_w = (const float*)d_in[13];
    const float* out_b = (const float*)d_in[14];
    const float* ln2_g = (const float*)d_in[15];
    const float* ln2_b = (const float*)d_in[16];
    const float* w1    = (const float*)d_in[17];
    const float* b1    = (const float*)d_in[18];
    const float* w2    = (const float*)d_in[19];
    const float* b2    = (const float*)d_in[20];
    const float* adw   = (const float*)d_in[21];
    const float* adb   = (const float*)d_in[22];
    const float* auw   = (const float*)d_in[23];
    const float* aub   = (const float*)d_in[24];
    float* out = (float*)d_out;

    void* p;
#define SYM(var, sym) cudaGetSymbolAddress(&p, sym); auto* var = (decltype(&sym[0]))p
    SYM(x1, g_x1);  SYM(x2, g_x2);
    SYM(hlc, g_hloc); SYM(hin, g_hin);
    SYM(mixh, g_mix_h);
    SYM(qkvrh, g_qkvr_h);
    SYM(qkv,  g_qkv);
    SYM(ysh, g_ys_h);
    SYM(h2h, g_h2_h);
    SYM(ffh, g_ff_h);
    SYM(x2h, g_x2h);
    SYM(adh, g_ad_h);
    SYM(uTh, g_uT_h);
    SYM(vTh, g_vT_h);
    SYM(owTh, g_owT_h);
    SYM(w1Th, g_w1T_h);
    SYM(w2Th, g_w2T_h);
    SYM(adwTh, g_adwT_h);
    SYM(auwTh, g_auwT_h);
#undef SYM
    f16* qf = qkv;
    f16* kf = qkv + (size_t)MM * CC;
    f16* vf = qkv + (size_t)2 * MM * CC;

    // variants: <BN, WM, WN, STAGES, BIAS, GELU, RES, OUTF32, OUTH>  (all 1-pass)
    auto mm_down = mm_h<64,  4, 2, 3, false, false, false, false, true >;
    auto mm_up   = mm_h<128, 2, 4, 2, false, false, false, false, true >;
    auto mm_oprj = mm_h<128, 2, 4, 3, true,  false, true,  true,  false>;
    auto mm_ffn1 = mm_h<128, 2, 4, 3, true,  true,  false, false, true >;
    auto mm_ffn2 = mm_h<128, 2, 4, 3, true,  false, true,  true,  true >;
    auto mm_add  = mm_h<32,  8, 1, 3, true,  true,  false, false, true >;
    auto mm_adu  = mm_h<128, 2, 4, 2, true,  false, true,  true,  false>;
    cudaFuncSetAttribute(mm_down, cudaFuncAttributeMaxDynamicSharedMemorySize, SMEMSZ(64,3));
    cudaFuncSetAttribute(mm_up,   cudaFuncAttributeMaxDynamicSharedMemorySize, SMEMSZ(128,2));
    cudaFuncSetAttribute(mm_oprj, cudaFuncAttributeMaxDynamicSharedMemorySize, SMEMSZ(128,3));
    cudaFuncSetAttribute(mm_ffn1, cudaFuncAttributeMaxDynamicSharedMemorySize, SMEMSZ(128,3));
    cudaFuncSetAttribute(mm_ffn2, cudaFuncAttributeMaxDynamicSharedMemorySize, SMEMSZ(128,3));
    cudaFuncSetAttribute(mm_add,  cudaFuncAttributeMaxDynamicSharedMemorySize, SMEMSZ(32,3));
    cudaFuncSetAttribute(mm_adu,  cudaFuncAttributeMaxDynamicSharedMemorySize, SMEMSZ(128,2));

    dim3 tb(16, 16);
    const bool dual = g_ss.ok;
    cudaStream_t s2 = dual ? g_ss.s : (cudaStream_t)0;
    cudaEvent_t eFork = g_ss.ev[0], eJoinT = g_ss.ev[1], eMixed = g_ss.ev[2],
                eQ = g_ss.ev[3], eComb = g_ss.ev[4], eA1 = g_ss.ev[5];

    // ---- main: qkv weight transposes ----
    transpose_split3<<<dim3(RR/32, CC/32, 3), tb>>>(qu, ku, vu, CC, RR, CC,
                                                    (size_t)RR*CC, uTh);

    // ---- fork: late-needed weight transposes on side stream ----
    if (dual) {
        cudaEventRecord(eFork, 0);
        cudaStreamWaitEvent(s2, eFork, 0);
    }
    transpose_split<<<dim3(CC/32,  CC/32), tb, 0, s2>>>(out_w, CC, CC, CC, owTh);
    transpose_split<<<dim3(FFD/32, CC/32), tb, 0, s2>>>(w1,  CC, FFD, CC,  w1Th);
    transpose_split<<<dim3(CC/32,  FFD/32),tb, 0, s2>>>(w2,  FFD, CC, FFD, w2Th);
    transpose_split<<<dim3(ARR/32, CC/32), tb, 0, s2>>>(adw, CC, ARR, CC,  adwTh);
    transpose_split<<<dim3(CC/32,  64/32), tb, 0, s2>>>(auw, ARR, CC, 64,  auwTh);
    if (dual) cudaEventRecord(eJoinT, s2);

    // ---- main chain ----
    transpose_split3<<<dim3(CC/32, RR/32, 3), tb>>>(qv, kvw, vvw, RR, CC, RR,
                                                    (size_t)CC*RR, vTh);
    ln1_mix_kernel<<<MM, 256>>>(x, ln1_g, ln1_b, tm_g, tm_b, mixh);

    // fused low-rank down-projections (1-pass): [M,1024]@[192,1024]^T
    mm_down<<<dim3(3, MM/128), 256, SMEMSZ(64,3)>>>(
        MM, 3*RR, CC, CC, 3*RR, 0, 0, 0, 0,
        mixh, uTh, nullptr, qkvrh, nullptr, nullptr);

    if (dual) {
        // q up-projection on side stream (consumed only by scan_apply)
        cudaEventRecord(eMixed, 0);
        cudaStreamWaitEvent(s2, eMixed, 0);
        mm_up<<<dim3(CC/128, MM/128, 1), 256, SMEMSZ(128,2), s2>>>(
            MM, CC, RR, 3*RR, CC, 0, 0, 0, 0,
            qkvrh, vTh, nullptr, qf, nullptr, nullptr);
        cudaEventRecord(eQ, s2);

        // k,v up-projections on main (z=0 -> k, z=1 -> v)
        mm_up<<<dim3(CC/128, MM/128, 2), 256, SMEMSZ(128,2)>>>(
            MM, CC, RR, 3*RR, CC, RR, (size_t)CC*RR, 0, (size_t)MM*CC,
            qkvrh + RR, vTh + (size_t)CC*RR, nullptr, kf, nullptr, nullptr);

        scan_local  <<<SEG*BB*(CC/8)/256, 256>>>(kf, vf, td, hlc);
        scan_combine<<<BC/256, 256>>>(hlc, h0, td, hin, out, (long)out_size);

        // apply split: half1 (b=4..7) on side, half0 (b=0..3) on main
        cudaStreamWaitEvent(0, eQ, 0);
        cudaEventRecord(eComb, 0);
        cudaStreamWaitEvent(s2, eComb, 0);
        scan_apply<<<SEG*4*(CC/8)/256, 256, 0, s2>>>(kf, vf, qf, td, hin, ysh, 4, 3, 2);
        cudaEventRecord(eA1, s2);
        scan_apply<<<SEG*4*(CC/8)/256, 256>>>(kf, vf, qf, td, hin, ysh, 0, 3, 2);

        // out-proj half0 (rows 0..MM/2) while apply half1 finishes
        cudaStreamWaitEvent(0, eJoinT, 0);
        mm_oprj<<<dim3(CC/128, (MM/2)/128), 256, SMEMSZ(128,3)>>>(
            MM/2, CC, CC, CC, 0, 0, 0, 0, 0,
            ysh, owTh, x1, nullptr, out_b, x);
        cudaStreamWaitEvent(0, eA1, 0);
        const size_t roff = (size_t)(MM/2) * CC;
        mm_oprj<<<dim3(CC/128, (MM/2)/128), 256, SMEMSZ(128,3)>>>(
            MM/2, CC, CC, CC, 0, 0, 0, 0, 0,
            ysh + roff, owTh, x1 + roff, nullptr, out_b, x + roff);
    } else {
        mm_up<<<dim3(CC/128, MM/128, 3), 256, SMEMSZ(128,2)>>>(
            MM, CC, RR, 3*RR, CC, RR, (size_t)CC*RR, 0, (size_t)MM*CC,
            qkvrh, vTh, nullptr, qkv, nullptr, nullptr);
        scan_local  <<<SEG*BB*(CC/8)/256, 256>>>(kf, vf, td, hlc);
        scan_combine<<<BC/256, 256>>>(hlc, h0, td, hin, out, (long)out_size);
        scan_apply  <<<SEG*BB*(CC/8)/256, 256>>>(kf, vf, qf, td, hin, ysh, 0, 7, 3);
        mm_oprj<<<dim3(CC/128, MM/128), 256, SMEMSZ(128,3)>>>(
            MM, CC, CC, CC, 0, 0, 0, 0, 0,
            ysh, owTh, x1, nullptr, out_b, x);
    }

    // h2 = LN2(x1) -> fp16
    ln_kernel<<<MM, 256>>>(x1, ln2_g, ln2_b, h2h);

    // FFN (1-pass)
    mm_ffn1<<<dim3(FFD/128, MM/128), 256, SMEMSZ(128,3)>>>(
        MM, FFD, CC, CC, FFD, 0, 0, 0, 0,
        h2h, w1Th, nullptr, ffh, b1, nullptr);
    mm_ffn2<<<dim3(CC/128, MM/128), 256, SMEMSZ(128,3)>>>(
        MM, CC, FFD, FFD, CC, 0, 0, 0, 0,
        ffh, w2Th, x2, x2h, b2, x1);

    // adapter: down (1-pass, N=32 pad 64) then up (1-pass) + residual
    mm_add<<<dim3(1, MM/128), 256, SMEMSZ(32,3)>>>(
        MM, ARR, CC, CC, 64, 0, 0, 0, 0,
        x2h, adwTh, nullptr, adh, adb, nullptr);
    mm_adu<<<dim3(CC/128, MM/128), 256, SMEMSZ(128,2)>>>(
        MM, CC, 64, 64, 0, 0, 0, 0, 0,
        adh, auwTh, out, nullptr, aub, x2);
}

// round 15
// speedup vs baseline: 1.0110x; 1.0110x over previous
#include <cuda_runtime.h>
#include <cuda_fp16.h>
#include <math.h>
#include <stdint.h>

// ---------------- problem constants (fixed shapes) ----------------
#define BB   8
#define TT   2048
#define CC   1024
#define RR   64
#define ARR  32
#define FFD  4096
#define MM   (BB*TT)        // 16384 rows
#define SEG  128
#define LSEG (TT/SEG)       // 16
#define BC   (BB*CC)        // 8192 channels

typedef __half f16;

// ---------------- side stream (created at load, NOT in kernel_launch) ---
struct SideStream {
    cudaStream_t s = 0;
    cudaEvent_t ev[4] = {};
    bool ok = false;
    SideStream() {
        ok = (cudaStreamCreateWithFlags(&s, cudaStreamNonBlocking) == cudaSuccess);
        for (int i = 0; i < 4 && ok; i++)
            ok = (cudaEventCreateWithFlags(&ev[i], cudaEventDisableTiming) == cudaSuccess);
    }
};
static SideStream g_ss;   // constructed before harness checkpoints

// ---------------- scratch (static device globals; no allocs) ------
__device__ __align__(256) float g_x1[MM*CC];
__device__ __align__(256) float g_x2[MM*CC];
__device__ __align__(256) float g_hloc[SEG*BC];
__device__ __align__(256) float g_hin [SEG*BC];

// fp16 activation buffers
__device__ __align__(256) f16 g_mix_h[MM*CC];
__device__ __align__(256) f16 g_qkvr_h[MM*3*RR];                 // [M,192] q|k|v
__device__ __align__(256) f16 g_qkv[(size_t)3*MM*CC];            // q,k,v fp16
__device__ __align__(256) f16 g_ys_h[MM*CC];
__device__ __align__(256) f16 g_h2_h[MM*CC];
__device__ __align__(256) f16 g_ff_h[(size_t)MM*FFD];
__device__ __align__(256) f16 g_x2h[MM*CC];
__device__ __align__(256) f16 g_ad_h[MM*64];                     // K padded 32->64

// fp16 transposed weights ([N,K] K-major)
__device__ __align__(256) f16 g_uT_h[3*RR*CC];                   // qu|ku|vu [192,1024]
__device__ __align__(256) f16 g_vT_h[3*CC*RR];                   // qv|kv|vv 3x[1024,64]
__device__ __align__(256) f16 g_owT_h[CC*CC];
__device__ __align__(256) f16 g_w1T_h[(size_t)FFD*CC];
__device__ __align__(256) f16 g_w2T_h[(size_t)CC*FFD];
__device__ __align__(256) f16 g_adwT_h[ARR*CC];
__device__ __align__(256) f16 g_auwT_h[CC*64];                   // K padded 32->64

// ---------------- PTX helpers ---------------------------------------
__device__ __forceinline__ uint32_t smem_u32(const void* p) {
    uint32_t a;
    asm("{ .reg .u64 t; cvta.to.shared.u64 t, %1; cvt.u32.u64 %0, t; }" : "=r"(a) : "l"(p));
    return a;
}
#define SWZ128(b) ((b) ^ (((b) >> 3) & 0x70))

__device__ __forceinline__ void cp16(uint32_t dst, const void* src) {
    asm volatile("cp.async.cg.shared.global [%0], [%1], 16;" :: "r"(dst), "l"(src));
}
#define CP_COMMIT()  asm volatile("cp.async.commit_group;" ::: "memory")

__device__ __forceinline__ void ldsm_x4(uint32_t* r, uint32_t addr) {
    asm volatile("ldmatrix.sync.aligned.m8n8.x4.shared.b16 {%0,%1,%2,%3}, [%4];"
                 : "=r"(r[0]), "=r"(r[1]), "=r"(r[2]), "=r"(r[3]) : "r"(addr));
}
__device__ __forceinline__ void mma16816(float* d, const uint32_t* a, const uint32_t* b) {
    asm volatile("mma.sync.aligned.m16n8k16.row.col.f32.f16.f16.f32 "
                 "{%0,%1,%2,%3}, {%4,%5,%6,%7}, {%8,%9}, {%0,%1,%2,%3};"
                 : "+f"(d[0]), "+f"(d[1]), "+f"(d[2]), "+f"(d[3])
                 : "r"(a[0]), "r"(a[1]), "r"(a[2]), "r"(a[3]), "r"(b[0]), "r"(b[1]));
}
__device__ __forceinline__ float tanh_fast(float x) {
    float y;
    asm("tanh.approx.f32 %0, %1;" : "=f"(y) : "f"(x));
    return y;
}

// ---------------- misc helpers --------------------------------------
__device__ __forceinline__ float gelu_tanh(float x) {
    float x3 = x * x * x;
    return 0.5f * x * (1.f + tanh_fast(0.7978845608028654f * (x + 0.044715f * x3)));
}
__device__ __forceinline__ float sigmoid_fast(float x) {
    return 0.5f + 0.5f * tanh_fast(0.5f * x);
}
__device__ __forceinline__ float block_sum_256(float val, float* sh) {
    int lane = threadIdx.x & 31;
#pragma unroll
    for (int o = 16; o > 0; o >>= 1) val += __shfl_xor_sync(0xffffffffu, val, o);
    if (lane == 0) sh[threadIdx.x >> 5] = val;
    __syncthreads();
    float r = (lane < 8) ? sh[lane] : 0.f;
#pragma unroll
    for (int o = 4; o > 0; o >>= 1) r += __shfl_xor_sync(0xffffffffu, r, o);
    r = __shfl_sync(0xffffffffu, r, 0);
    __syncthreads();
    return r;
}

// double-LN of one row's float4 slice (two chained LayerNorms)
__device__ __forceinline__ float4 ln2x(float4 v,
                                       const float* __restrict__ g1, const float* __restrict__ b1,
                                       const float* __restrict__ g2, const float* __restrict__ b2,
                                       int tid, float* sh)
{
#pragma unroll
    for (int pass = 0; pass < 2; pass++) {
        const float* gg = pass ? g2 : g1;
        const float* bb = pass ? b2 : b1;
        float mean = block_sum_256(v.x + v.y + v.z + v.w, sh) * (1.f / CC);
        float dx = v.x - mean, dy = v.y - mean, dz = v.z - mean, dw = v.w - mean;
        float var = block_sum_256(dx*dx + dy*dy + dz*dz + dw*dw, sh) * (1.f / CC);
        float rstd = rsqrtf(var + 1e-5f);
        float4 gv = *(const float4*)(gg + tid * 4);
        float4 bv = *(const float4*)(bb + tid * 4);
        v.x = dx * rstd * gv.x + bv.x;
        v.y = dy * rstd * gv.y + bv.y;
        v.z = dz * rstd * gv.z + bv.z;
        v.w = dw * rstd * gv.w + bv.w;
    }
    return v;
}

// ---------------- fused LN1(LN1(x)) + token-shift mix -> fp16 --------
__global__ void ln1_mix_kernel(const float* __restrict__ x,
                               const float* __restrict__ g1, const float* __restrict__ b1,
                               const float* __restrict__ g2, const float* __restrict__ b2,
                               f16* __restrict__ mh)
{
    __shared__ float sh[8];
    int row = blockIdx.x;
    int tid = threadIdx.x;
    int t = row & (TT - 1);
    float4 vc = *(const float4*)(x + (size_t)row * CC + tid * 4);
    vc = ln2x(vc, g1, b1, g2, b2, tid, sh);
    float4 vp = make_float4(0.f, 0.f, 0.f, 0.f);
    if (t > 0) {   // uniform across block
        vp = *(const float4*)(x + (size_t)(row - 1) * CC + tid * 4);
        vp = ln2x(vp, g1, b1, g2, b2, tid, sh);
    }
    __half2 h01 = __floats2half2_rn(0.5f * (vc.x + vp.x), 0.5f * (vc.y + vp.y));
    __half2 h23 = __floats2half2_rn(0.5f * (vc.z + vp.z), 0.5f * (vc.w + vp.w));
    uint2 u; u.x = *(uint32_t*)&h01; u.y = *(uint32_t*)&h23;
    *(uint2*)(mh + (size_t)row * CC + tid * 4) = u;
}

// ---------------- LayerNorm (single, fp16 out) -----------------------
__global__ void ln_kernel(const float* __restrict__ x,
                          const float* __restrict__ g1, const float* __restrict__ b1,
                          f16* __restrict__ oh)
{
    __shared__ float sh[8];
    int row = blockIdx.x;
    int tid = threadIdx.x;
    float4 v = *(const float4*)(x + (size_t)row * CC + tid * 4);
    float mean = block_sum_256(v.x + v.y + v.z + v.w, sh) * (1.f / CC);
    float dx = v.x - mean, dy = v.y - mean, dz = v.z - mean, dw = v.w - mean;
    float var = block_sum_256(dx*dx + dy*dy + dz*dz + dw*dw, sh) * (1.f / CC);
    float rstd = rsqrtf(var + 1e-5f);
    float4 gv = *(const float4*)(g1 + tid * 4);
    float4 bv = *(const float4*)(b1 + tid * 4);
    __half2 h01 = __floats2half2_rn(dx * rstd * gv.x + bv.x, dy * rstd * gv.y + bv.y);
    __half2 h23 = __floats2half2_rn(dz * rstd * gv.z + bv.z, dw * rstd * gv.w + bv.w);
    uint2 u; u.x = *(uint32_t*)&h01; u.y = *(uint32_t*)&h23;
    *(uint2*)(oh + (size_t)row * CC + tid * 4) = u;
}

// ---------------- weight transpose (fp16 hi only) ---------------------
__global__ void transpose_split(const float* __restrict__ w, int R, int S, int ldout,
                                f16* __restrict__ th)
{
    __shared__ float t[32][33];
    int s0 = blockIdx.x * 32, r0 = blockIdx.y * 32;
    int tx = threadIdx.x, ty = threadIdx.y;   // (16,16)
#pragma unroll
    for (int i = ty; i < 32; i += 16) {
        float2 v = make_float2(0.f, 0.f);
        if (r0 + i < R) v = *(const float2*)(w + (size_t)(r0 + i) * S + s0 + tx * 2);
        t[i][tx*2] = v.x; t[i][tx*2+1] = v.y;
    }
    __syncthreads();
#pragma unroll
    for (int i = ty; i < 32; i += 16) {
        float a = t[tx*2][i], b = t[tx*2+1][i];
        size_t o = (size_t)(s0 + i) * ldout + r0 + tx * 2;
        __half2 hh = __floats2half2_rn(a, b);
        *(__half2*)(th + o) = hh;
    }
}

__global__ void transpose_split3(const float* __restrict__ w0, const float* __restrict__ w1,
                                 const float* __restrict__ w2,
                                 int R, int S, int ldout, size_t zoff,
                                 f16* __restrict__ th)
{
    __shared__ float t[32][33];
    const float* w = (blockIdx.z == 0) ? w0 : (blockIdx.z == 1) ? w1 : w2;
    th += blockIdx.z * zoff;
    int s0 = blockIdx.x * 32, r0 = blockIdx.y * 32;
    int tx = threadIdx.x, ty = threadIdx.y;
#pragma unroll
    for (int i = ty; i < 32; i += 16) {
        float2 v = make_float2(0.f, 0.f);
        if (r0 + i < R) v = *(const float2*)(w + (size_t)(r0 + i) * S + s0 + tx * 2);
        t[i][tx*2] = v.x; t[i][tx*2+1] = v.y;
    }
    __syncthreads();
#pragma unroll
    for (int i = ty; i < 32; i += 16) {
        float a = t[tx*2][i], b = t[tx*2+1][i];
        size_t o = (size_t)(s0 + i) * ldout + r0 + tx * 2;
        __half2 hh = __floats2half2_rn(a, b);
        *(__half2*)(th + o) = hh;
    }
}

// ---------------- HMMA fp16 GEMM (R8-proven shapes, 1-pass) -----------
template<int BN, int WMS, int WNS, int S,
         bool BIAS, bool GELU, bool RES, bool OUTF32, bool OUTH>
__global__ void __launch_bounds__(256, 2)
mm_h(int M, int N, int K, int lda, int ldh,
     size_t az, size_t bz, size_t czf, size_t czh,
     const f16* __restrict__ Ah, const f16* __restrict__ Bh,
     float* __restrict__ C, f16* __restrict__ Ch,
     const float* __restrict__ bias, const float* __restrict__ res)
{
    constexpr int BM = 128;
    constexpr int NTH = 256;
    constexpr int TMW = BM / WMS;
    constexpr int TNW = BN / WNS;
    constexpr int MT = TMW / 16;
    constexpr int NT = TNW / 8;
    constexpr int A_BYTES = BM * 128;
    constexpr int B_BYTES = BN * 128;
    constexpr int STAGE   = A_BYTES + B_BYTES;

    extern __shared__ char smem[];
    const uint32_t sb = smem_u32(smem);

    const int z = blockIdx.z;
    Ah += (size_t)z * az;
    Bh += (size_t)z * bz;
    if (OUTF32) C  += (size_t)z * czf;
    if (OUTH)   Ch += (size_t)z * czh;

    const int tid  = threadIdx.x;
    const int lane = tid & 31;
    const int warp = tid >> 5;
    const int wm   = warp / WNS;
    const int wn   = warp % WNS;
    const int brow = blockIdx.y * BM;
    const int bcol = blockIdx.x * BN;
    const int NK   = K >> 6;

    float acc[MT][NT][4];
#pragma unroll
    for (int i = 0; i < MT; i++)
#pragma unroll
        for (int j = 0; j < NT; j++)
#pragma unroll
            for (int e = 0; e < 4; e++) acc[i][j][e] = 0.f;

    auto load_stage = [&](int kc, int s) {
        uint32_t base = sb + s * STAGE;
#pragma unroll 2
        for (int i = tid; i < BM * 8; i += NTH) {
            int r = i >> 3, j = i & 7;
            size_t go = (size_t)(brow + r) * lda + (size_t)kc * 64 + j * 8;
            uint32_t sw = SWZ128((uint32_t)(r * 128 + j * 16));
            cp16(base + sw, Ah + go);
        }
#pragma unroll 2
        for (int i = tid; i < BN * 8; i += NTH) {
            int r = i >> 3, j = i & 7;
            size_t go = (size_t)(bcol + r) * K + (size_t)kc * 64 + j * 8;
            uint32_t sw = SWZ128((uint32_t)(r * 128 + j * 16));
            cp16(base + A_BYTES + sw, Bh + go);
        }
        CP_COMMIT();
    };

    const int npre = (S - 1 < NK) ? S - 1 : NK;
    for (int i = 0; i < npre; i++) load_stage(i, i);
    for (int i = npre; i < S - 1; i++) CP_COMMIT();

    for (int kc = 0; kc < NK; kc++) {
        asm volatile("cp.async.wait_group %0;" :: "n"(S - 2) : "memory");
        __syncthreads();
        if (kc + S - 1 < NK) load_stage(kc + S - 1, (kc + S - 1) % S);
        else                 CP_COMMIT();

        const uint32_t st = sb + (kc % S) * STAGE;
#pragma unroll
        for (int ks = 0; ks < 4; ks++) {
            uint32_t a_h[MT][4];
#pragma unroll
            for (int mt = 0; mt < MT; mt++) {
                int r = wm * TMW + mt * 16 + (lane & 15);
                uint32_t off = SWZ128((uint32_t)(r * 128 + ks * 32 + ((lane >> 4) << 4)));
                ldsm_x4(a_h[mt], st + off);
            }
            uint32_t b_h[NT][2];
#pragma unroll
            for (int p = 0; p < NT / 2; p++) {
                int r = wn * TNW + p * 16 + (lane & 7) + ((lane >> 4) << 3);
                uint32_t off = SWZ128((uint32_t)(r * 128 + ks * 32 + (((lane >> 3) & 1) << 4)));
                uint32_t t4[4];
                ldsm_x4(t4, st + A_BYTES + off);
                b_h[2*p][0] = t4[0]; b_h[2*p][1] = t4[1];
                b_h[2*p+1][0] = t4[2]; b_h[2*p+1][1] = t4[3];
            }
#pragma unroll
            for (int mt = 0; mt < MT; mt++)
#pragma unroll
                for (int nt = 0; nt < NT; nt++) mma16816(acc[mt][nt], a_h[mt], b_h[nt]);
        }
    }

    // ---- epilogue ----
#pragma unroll
    for (int mt = 0; mt < MT; mt++) {
#pragma unroll
        for (int nt = 0; nt < NT; nt++) {
            int r0 = brow + wm * TMW + mt * 16 + (lane >> 2);
            int cg = bcol + wn * TNW + nt * 8 + ((lane & 3) << 1);
#pragma unroll
            for (int h = 0; h < 2; h++) {
                int r = r0 + h * 8;
                float v0 = acc[mt][nt][2*h], v1 = acc[mt][nt][2*h+1];
                if (BIAS) { v0 += bias[cg]; v1 += bias[cg + 1]; }
                if (GELU) { v0 = gelu_tanh(v0); v1 = gelu_tanh(v1); }
                if (RES) {
                    float2 rv = *(const float2*)(res + (size_t)r * N + cg);
                    v0 += rv.x; v1 += rv.y;
                }
                if (OUTF32)
                    *(float2*)(C + (size_t)r * N + cg) = make_float2(v0, v1);
                if (OUTH) {
                    __half2 hh = __floats2half2_rn(v0, v1);
                    *(__half2*)(Ch + (size_t)r * ldh + cg) = hh;
                }
            }
        }
    }
    if (OUTH && ldh > N) {
        int pads = (ldh - N) >> 3;
        for (int i = tid; i < BM * pads; i += NTH) {
            int r = brow + i / pads;
            int c = N + (i % pads) * 8;
            uint4 zv = make_uint4(0, 0, 0, 0);
            *(uint4*)(Ch + (size_t)r * ldh + c) = zv;
        }
    }
}

// ---------------- segmented scan (8 channels/thread, uint4 I/O) ------
__global__ void scan_local(const f16* __restrict__ k, const f16* __restrict__ v,
                           const float* __restrict__ td, float* __restrict__ hloc)
{
    int idx = blockIdx.x * blockDim.x + threadIdx.x;   // < SEG*BB*(CC/8)
    int c8 = idx & (CC/8 - 1);
    int rest = idx >> 7;
    int b = rest & (BB - 1);
    int seg = rest >> 3;
    int c0 = c8 * 8;
    float4 t0 = *(const float4*)(td + c0);
    float4 t1 = *(const float4*)(td + c0 + 4);
    float d[8] = {expf(-expf(t0.x)), expf(-expf(t0.y)), expf(-expf(t0.z)), expf(-expf(t0.w)),
                  expf(-expf(t1.x)), expf(-expf(t1.y)), expf(-expf(t1.z)), expf(-expf(t1.w))};
    float h[8] = {0.f,0.f,0.f,0.f,0.f,0.f,0.f,0.f};
    size_t base = ((size_t)(b * TT + seg * LSEG)) * CC + c0;
#pragma unroll 4
    for (int i = 0; i < LSEG; i++) {
        uint4 ku = *(const uint4*)(k + base);
        uint4 vu = *(const uint4*)(v + base);
        const __half2* kh = (const __half2*)&ku;
        const __half2* vh = (const __half2*)&vu;
#pragma unroll
        for (int j = 0; j < 4; j++) {
            float2 kf = __half22float2(kh[j]);
            float2 vf = __half22float2(vh[j]);
            h[2*j]   = d[2*j]   * h[2*j]   + kf.x * vf.x;
            h[2*j+1] = d[2*j+1] * h[2*j+1] + kf.y * vf.y;
        }
        base += CC;
    }
    int o = seg * BC + b * CC + c0;
    *(float4*)(hloc + o)     = make_float4(h[0], h[1], h[2], h[3]);
    *(float4*)(hloc + o + 4) = make_float4(h[4], h[5], h[6], h[7]);
}

__global__ void scan_combine(const float* __restrict__ hloc, const float* __restrict__ h0,
                             const float* __restrict__ td, float* __restrict__ hin,
                             float* __restrict__ out, long out_size)
{
    int rem = blockIdx.x * blockDim.x + threadIdx.x;   // < BC
    int c = rem & (CC - 1);
    float e = expf(td[c]);
    float dL = expf(-(float)LSEG * e);
    float h = h0[rem];
#pragma unroll
    for (int s = 0; s < SEG; s++) {
        hin[s * BC + rem] = h;
        h = dL * h + hloc[s * BC + rem];
    }
    if (out_size >= (long)MM * CC + BC)
        out[(size_t)MM * CC + rem] = h;
}

__global__ void scan_apply(const f16* __restrict__ k, const f16* __restrict__ v,
                           const f16* __restrict__ q, const float* __restrict__ td,
                           const float* __restrict__ hin, f16* __restrict__ yh)
{
    int idx = blockIdx.x * blockDim.x + threadIdx.x;
    int c8 = idx & (CC/8 - 1);
    int rest = idx >> 7;
    int b = rest & (BB - 1);
    int seg = rest >> 3;
    int c0 = c8 * 8;
    float4 t0 = *(const float4*)(td + c0);
    float4 t1 = *(const float4*)(td + c0 + 4);
    float d[8] = {expf(-expf(t0.x)), expf(-expf(t0.y)), expf(-expf(t0.z)), expf(-expf(t0.w)),
                  expf(-expf(t1.x)), expf(-expf(t1.y)), expf(-expf(t1.z)), expf(-expf(t1.w))};
    int ho = seg * BC + b * CC + c0;
    float4 h03 = *(const float4*)(hin + ho);
    float4 h47 = *(const float4*)(hin + ho + 4);
    float h[8] = {h03.x, h03.y, h03.z, h03.w, h47.x, h47.y, h47.z, h47.w};
    size_t base = ((size_t)(b * TT + seg * LSEG)) * CC + c0;
#pragma unroll 4
    for (int i = 0; i < LSEG; i++) {
        uint4 ku = *(const uint4*)(k + base);
        uint4 vu = *(const uint4*)(v + base);
        uint4 qu = *(const uint4*)(q + base);
        const __half2* kh = (const __half2*)&ku;
        const __half2* vh = (const __half2*)&vu;
        const __half2* qh = (const __half2*)&qu;
        uint4 yo;
        uint32_t* yp = (uint32_t*)&yo;
#pragma unroll
        for (int j = 0; j < 4; j++) {
            float2 kf = __half22float2(kh[j]);
            float2 vf = __half22float2(vh[j]);
            float2 qf = __half22float2(qh[j]);
            h[2*j]   = d[2*j]   * h[2*j]   + kf.x * vf.x;
            h[2*j+1] = d[2*j+1] * h[2*j+1] + kf.y * vf.y;
            __half2 yv = __floats2half2_rn(h[2*j]   * sigmoid_fast(qf.x),
                                           h[2*j+1] * sigmoid_fast(qf.y));
            yp[j] = *(uint32_t*)&yv;
        }
        *(uint4*)(yh + base) = yo;
        base += CC;
    }
}

// ---------------- launch ----------------------------------------------
#define SMEMSZ(BN, S) ((S) * ((128 + (BN)) * 128))

extern "C" void kernel_launch(void* const* d_in, const int* in_sizes, int n_in,
                              void* d_out, int out_size)
{
    const float* x     = (const float*)d_in[0];
    const float* h0    = (const float*)d_in[1];
    const float* ln1_g = (const float*)d_in[2];
    const float* ln1_b = (const float*)d_in[3];
    const float* tm_g  = (const float*)d_in[4];
    const float* tm_b  = (const float*)d_in[5];
    const float* qu    = (const float*)d_in[6];
    const float* qv    = (const float*)d_in[7];
    const float* ku    = (const float*)d_in[8];
    const float* kvw   = (const float*)d_in[9];
    const float* vu    = (const float*)d_in[10];
    const float* vvw   = (const float*)d_in[11];
    const float* td    = (const float*)d_in[12];
    const float* out_w = (const float*)d_in[13];
    const float* out_b = (const float*)d_in[14];
    const float* ln2_g = (const float*)d_in[15];
    const float* ln2_b = (const float*)d_in[16];
    const float* w1    = (const float*)d_in[17];
    const float* b1    = (const float*)d_in[18];
    const float* w2    = (const float*)d_in[19];
    const float* b2    = (const float*)d_in[20];
    const float* adw   = (const float*)d_in[21];
    const float* adb   = (const float*)d_in[22];
    const float* auw   = (const float*)d_in[23];
    const float* aub   = (const float*)d_in[24];
    float* out = (float*)d_out;

    void* p;
#define SYM(var, sym) cudaGetSymbolAddress(&p, sym); auto* var = (decltype(&sym[0]))p
    SYM(x1, g_x1);  SYM(x2, g_x2);
    SYM(hlc, g_hloc); SYM(hin, g_hin);
    SYM(mixh, g_mix_h);
    SYM(qkvrh, g_qkvr_h);
    SYM(qkv,  g_qkv);
    SYM(ysh, g_ys_h);
    SYM(h2h, g_h2_h);
    SYM(ffh, g_ff_h);
    SYM(x2h, g_x2h);
    SYM(adh, g_ad_h);
    SYM(uTh, g_uT_h);
    SYM(vTh, g_vT_h);
    SYM(owTh, g_owT_h);
    SYM(w1Th, g_w1T_h);
    SYM(w2Th, g_w2T_h);
    SYM(adwTh, g_adwT_h);
    SYM(auwTh, g_auwT_h);
#undef SYM
    f16* qf = qkv;
    f16* kf = qkv + (size_t)MM * CC;
    f16* vf = qkv + (size_t)2 * MM * CC;

    // variants: <BN, WM, WN, STAGES, BIAS, GELU, RES, OUTF32, OUTH>  (all 1-pass)
    auto mm_down = mm_h<64,  4, 2, 3, false, false, false, false, true >;
    auto mm_up   = mm_h<128, 2, 4, 2, false, false, false, false, true >;
    auto mm_oprj = mm_h<128, 2, 4, 3, true,  false, true,  true,  false>;
    auto mm_ffn1 = mm_h<128, 2, 4, 3, true,  true,  false, false, true >;
    auto mm_ffn2 = mm_h<128, 2, 4, 3, true,  false, true,  true,  true >;
    auto mm_add  = mm_h<32,  8, 1, 3, true,  true,  false, false, true >;
    auto mm_adu  = mm_h<128, 2, 4, 2, true,  false, true,  true,  false>;
    cudaFuncSetAttribute(mm_down, cudaFuncAttributeMaxDynamicSharedMemorySize, SMEMSZ(64,3));
    cudaFuncSetAttribute(mm_up,   cudaFuncAttributeMaxDynamicSharedMemorySize, SMEMSZ(128,2));
    cudaFuncSetAttribute(mm_oprj, cudaFuncAttributeMaxDynamicSharedMemorySize, SMEMSZ(128,3));
    cudaFuncSetAttribute(mm_ffn1, cudaFuncAttributeMaxDynamicSharedMemorySize, SMEMSZ(128,3));
    cudaFuncSetAttribute(mm_ffn2, cudaFuncAttributeMaxDynamicSharedMemorySize, SMEMSZ(128,3));
    cudaFuncSetAttribute(mm_add,  cudaFuncAttributeMaxDynamicSharedMemorySize, SMEMSZ(32,3));
    cudaFuncSetAttribute(mm_adu,  cudaFuncAttributeMaxDynamicSharedMemorySize, SMEMSZ(128,2));

    dim3 tb(16, 16);
    const bool dual = g_ss.ok;
    cudaStream_t s2 = dual ? g_ss.s : (cudaStream_t)0;
    cudaEvent_t eFork = g_ss.ev[0], eJoinT = g_ss.ev[1], eMixed = g_ss.ev[2],
                eQ = g_ss.ev[3];

    // ---- main: qkv weight transposes ----
    transpose_split3<<<dim3(RR/32, CC/32, 3), tb>>>(qu, ku, vu, CC, RR, CC,
                                                    (size_t)RR*CC, uTh);

    // ---- fork: late-needed weight transposes on side stream ----
    if (dual) {
        cudaEventRecord(eFork, 0);
        cudaStreamWaitEvent(s2, eFork, 0);
    }
    transpose_split<<<dim3(CC/32,  CC/32), tb, 0, s2>>>(out_w, CC, CC, CC, owTh);
    transpose_split<<<dim3(FFD/32, CC/32), tb, 0, s2>>>(w1,  CC, FFD, CC,  w1Th);
    transpose_split<<<dim3(CC/32,  FFD/32),tb, 0, s2>>>(w2,  FFD, CC, FFD, w2Th);
    transpose_split<<<dim3(ARR/32, CC/32), tb, 0, s2>>>(adw, CC, ARR, CC,  adwTh);
    transpose_split<<<dim3(CC/32,  64/32), tb, 0, s2>>>(auw, ARR, CC, 64,  auwTh);

    // ---- main chain ----
    transpose_split3<<<dim3(CC/32, RR/32, 3), tb>>>(qv, kvw, vvw, RR, CC, RR,
                                                    (size_t)CC*RR, vTh);
    ln1_mix_kernel<<<MM, 256>>>(x, ln1_g, ln1_b, tm_g, tm_b, mixh);

    // fused low-rank down-projections (1-pass): [M,1024]@[192,1024]^T
    mm_down<<<dim3(3, MM/128), 256, SMEMSZ(64,3)>>>(
        MM, 3*RR, CC, CC, 3*RR, 0, 0, 0, 0,
        mixh, uTh, nullptr, qkvrh, nullptr, nullptr);

    if (dual) {
        // q up-projection on side stream (consumed only by scan_apply);
        // overlaps with k,v up + scan_local + scan_combine on main.
        cudaEventRecord(eMixed, 0);
        cudaStreamWaitEvent(s2, eMixed, 0);
        mm_up<<<dim3(CC/128, MM/128, 1), 256, SMEMSZ(128,2), s2>>>(
            MM, CC, RR, 3*RR, CC, 0, 0, 0, 0,
            qkvrh, vTh, nullptr, qf, nullptr, nullptr);
        cudaEventRecord(eQ, s2);

        // k,v up-projections on main (z=0 -> k, z=1 -> v)
        mm_up<<<dim3(CC/128, MM/128, 2), 256, SMEMSZ(128,2)>>>(
            MM, CC, RR, 3*RR, CC, RR, (size_t)CC*RR, 0, (size_t)MM*CC,
            qkvrh + RR, vTh + (size_t)CC*RR, nullptr, kf, nullptr, nullptr);

        scan_local  <<<SEG*BB*(CC/8)/256, 256>>>(kf, vf, td, hlc);
        scan_combine<<<BC/256, 256>>>(hlc, h0, td, hin, out, (long)out_size);

        cudaStreamWaitEvent(0, eQ, 0);
        scan_apply<<<SEG*BB*(CC/8)/256, 256>>>(kf, vf, qf, td, hin, ysh);
        if (dual) cudaEventRecord(eJoinT, s2);   // side stream idle after q-up
        cudaStreamWaitEvent(0, eJoinT, 0);       // transposes done before oprj/ffn
    } else {
        mm_up<<<dim3(CC/128, MM/128, 3), 256, SMEMSZ(128,2)>>>(
            MM, CC, RR, 3*RR, CC, RR, (size_t)CC*RR, 0, (size_t)MM*CC,
            qkvrh, vTh, nullptr, qkv, nullptr, nullptr);
        scan_local  <<<SEG*BB*(CC/8)/256, 256>>>(kf, vf, td, hlc);
        scan_combine<<<BC/256, 256>>>(hlc, h0, td, hin, out, (long)out_size);
        scan_apply  <<<SEG*BB*(CC/8)/256, 256>>>(kf, vf, qf, td, hin, ysh);
    }

    // out-proj (1-pass) + bias + residual(x) -> x1 fp32
    mm_oprj<<<dim3(CC/128, MM/128), 256, SMEMSZ(128,3)>>>(
        MM, CC, CC, CC, 0, 0, 0, 0, 0,
        ysh, owTh, x1, nullptr, out_b, x);

    // h2 = LN2(x1) -> fp16
    ln_kernel<<<MM, 256>>>(x1, ln2_g, ln2_b, h2h);

    // FFN (1-pass)
    mm_ffn1<<<dim3(FFD/128, MM/128), 256, SMEMSZ(128,3)>>>(
        MM, FFD, CC, CC, FFD, 0, 0, 0, 0,
        h2h, w1Th, nullptr, ffh, b1, nullptr);
    mm_ffn2<<<dim3(CC/128, MM/128), 256, SMEMSZ(128,3)>>>(
        MM, CC, FFD, FFD, CC, 0, 0, 0, 0,
        ffh, w2Th, x2, x2h, b2, x1);

    // adapter: down (1-pass, N=32 pad 64) then up (1-pass) + residual
    mm_add<<<dim3(1, MM/128), 256, SMEMSZ(32,3)>>>(
        MM, ARR, CC, CC, 64, 0, 0, 0, 0,
        x2h, adwTh, nullptr, adh, adb, nullptr);
    mm_adu<<<dim3(CC/128, MM/128), 256, SMEMSZ(128,2)>>>(
        MM, CC, 64, 64, 0, 0, 0, 0, 0,
        adh, auwTh, out, nullptr, aub, x2);
}

// round 16
// speedup vs baseline: 1.0311x; 1.0199x over previous
#include <cuda_runtime.h>
#include <cuda_fp16.h>
#include <math.h>
#include <stdint.h>

// ---------------- problem constants (fixed shapes) ----------------
#define BB   8
#define TT   2048
#define CC   1024
#define RR   64
#define ARR  32
#define FFD  4096
#define MM   (BB*TT)        // 16384 rows
#define SEG  128
#define LSEG (TT/SEG)       // 16
#define BC   (BB*CC)        // 8192 channels

typedef __half f16;

// ---------------- side stream (created at load, NOT in kernel_launch) ---
struct SideStream {
    cudaStream_t s = 0;
    cudaEvent_t ev[2] = {};
    bool ok = false;
    SideStream() {
        ok = (cudaStreamCreateWithFlags(&s, cudaStreamNonBlocking) == cudaSuccess);
        for (int i = 0; i < 2 && ok; i++)
            ok = (cudaEventCreateWithFlags(&ev[i], cudaEventDisableTiming) == cudaSuccess);
    }
};
static SideStream g_ss;   // constructed before harness checkpoints

// ---------------- scratch (static device globals; no allocs) ------
__device__ __align__(256) float g_x1[MM*CC];
__device__ __align__(256) float g_x2[MM*CC];
__device__ __align__(256) float g_hloc[SEG*BC];
__device__ __align__(256) float g_hin [SEG*BC];

// fp16 activation buffers
__device__ __align__(256) f16 g_mix_h[MM*CC];
__device__ __align__(256) f16 g_qkvr_h[MM*3*RR];                 // [M,192] q|k|v
__device__ __align__(256) f16 g_qkv[(size_t)3*MM*CC];            // q,k,v fp16
__device__ __align__(256) f16 g_ys_h[MM*CC];
__device__ __align__(256) f16 g_h2_h[MM*CC];
__device__ __align__(256) f16 g_ff_h[(size_t)MM*FFD];
__device__ __align__(256) f16 g_x2h[MM*CC];
__device__ __align__(256) f16 g_ad_h[MM*64];                     // K padded 32->64

// fp16 transposed weights ([N,K] K-major)
__device__ __align__(256) f16 g_uT_h[3*RR*CC];                   // qu|ku|vu [192,1024]
__device__ __align__(256) f16 g_vT_h[3*CC*RR];                   // qv|kv|vv 3x[1024,64]
__device__ __align__(256) f16 g_owT_h[CC*CC];
__device__ __align__(256) f16 g_w1T_h[(size_t)FFD*CC];
__device__ __align__(256) f16 g_w2T_h[(size_t)CC*FFD];
__device__ __align__(256) f16 g_adwT_h[ARR*CC];
__device__ __align__(256) f16 g_auwT_h[CC*64];                   // K padded 32->64

// ---------------- PTX helpers ---------------------------------------
__device__ __forceinline__ uint32_t smem_u32(const void* p) {
    uint32_t a;
    asm("{ .reg .u64 t; cvta.to.shared.u64 t, %1; cvt.u32.u64 %0, t; }" : "=r"(a) : "l"(p));
    return a;
}
#define SWZ128(b) ((b) ^ (((b) >> 3) & 0x70))

__device__ __forceinline__ void cp16(uint32_t dst, const void* src) {
    asm volatile("cp.async.cg.shared.global [%0], [%1], 16;" :: "r"(dst), "l"(src));
}
#define CP_COMMIT()  asm volatile("cp.async.commit_group;" ::: "memory")

__device__ __forceinline__ void ldsm_x4(uint32_t* r, uint32_t addr) {
    asm volatile("ldmatrix.sync.aligned.m8n8.x4.shared.b16 {%0,%1,%2,%3}, [%4];"
                 : "=r"(r[0]), "=r"(r[1]), "=r"(r[2]), "=r"(r[3]) : "r"(addr));
}
__device__ __forceinline__ void mma16816(float* d, const uint32_t* a, const uint32_t* b) {
    asm volatile("mma.sync.aligned.m16n8k16.row.col.f32.f16.f16.f32 "
                 "{%0,%1,%2,%3}, {%4,%5,%6,%7}, {%8,%9}, {%0,%1,%2,%3};"
                 : "+f"(d[0]), "+f"(d[1]), "+f"(d[2]), "+f"(d[3])
                 : "r"(a[0]), "r"(a[1]), "r"(a[2]), "r"(a[3]), "r"(b[0]), "r"(b[1]));
}
__device__ __forceinline__ float tanh_fast(float x) {
    float y;
    asm("tanh.approx.f32 %0, %1;" : "=f"(y) : "f"(x));
    return y;
}

// ---------------- misc helpers --------------------------------------
__device__ __forceinline__ float gelu_tanh(float x) {
    float x3 = x * x * x;
    return 0.5f * x * (1.f + tanh_fast(0.7978845608028654f * (x + 0.044715f * x3)));
}
__device__ __forceinline__ float sigmoid_fast(float x) {
    return 0.5f + 0.5f * tanh_fast(0.5f * x);
}
__device__ __forceinline__ float block_sum_256(float val, float* sh) {
    int lane = threadIdx.x & 31;
#pragma unroll
    for (int o = 16; o > 0; o >>= 1) val += __shfl_xor_sync(0xffffffffu, val, o);
    if (lane == 0) sh[threadIdx.x >> 5] = val;
    __syncthreads();
    float r = (lane < 8) ? sh[lane] : 0.f;
#pragma unroll
    for (int o = 4; o > 0; o >>= 1) r += __shfl_xor_sync(0xffffffffu, r, o);
    r = __shfl_sync(0xffffffffu, r, 0);
    __syncthreads();
    return r;
}

// double-LN of one row's float4 slice (two chained LayerNorms)
__device__ __forceinline__ float4 ln2x(float4 v,
                                       const float* __restrict__ g1, const float* __restrict__ b1,
                                       const float* __restrict__ g2, const float* __restrict__ b2,
                                       int tid, float* sh)
{
#pragma unroll
    for (int pass = 0; pass < 2; pass++) {
        const float* gg = pass ? g2 : g1;
        const float* bb = pass ? b2 : b1;
        float mean = block_sum_256(v.x + v.y + v.z + v.w, sh) * (1.f / CC);
        float dx = v.x - mean, dy = v.y - mean, dz = v.z - mean, dw = v.w - mean;
        float var = block_sum_256(dx*dx + dy*dy + dz*dz + dw*dw, sh) * (1.f / CC);
        float rstd = rsqrtf(var + 1e-5f);
        float4 gv = *(const float4*)(gg + tid * 4);
        float4 bv = *(const float4*)(bb + tid * 4);
        v.x = dx * rstd * gv.x + bv.x;
        v.y = dy * rstd * gv.y + bv.y;
        v.z = dz * rstd * gv.z + bv.z;
        v.w = dw * rstd * gv.w + bv.w;
    }
    return v;
}

// ---- fused double-LN + token-shift mix, 2 rows/block (shares LN(r0)) ----
__global__ void ln1_mix_kernel(const float* __restrict__ x,
                               const float* __restrict__ g1, const float* __restrict__ b1,
                               const float* __restrict__ g2, const float* __restrict__ b2,
                               f16* __restrict__ mh)
{
    __shared__ float sh[8];
    int r0 = blockIdx.x * 2;            // even row; r1 = r0 + 1
    int tid = threadIdx.x;
    int t0 = r0 & (TT - 1);             // even; prev valid iff t0 > 0

    // LN of previous row (for r0's mix), only if t0 > 0
    float4 vp = make_float4(0.f, 0.f, 0.f, 0.f);
    if (t0 > 0) {
        vp = *(const float4*)(x + (size_t)(r0 - 1) * CC + tid * 4);
        vp = ln2x(vp, g1, b1, g2, b2, tid, sh);
    }
    // LN of row r0 (used for r0's own mix and as r1's prev)
    float4 v0 = *(const float4*)(x + (size_t)r0 * CC + tid * 4);
    v0 = ln2x(v0, g1, b1, g2, b2, tid, sh);
    // LN of row r1
    float4 v1 = *(const float4*)(x + (size_t)(r0 + 1) * CC + tid * 4);
    v1 = ln2x(v1, g1, b1, g2, b2, tid, sh);

    // mix[r0] = 0.5*(v0 + vp);  mix[r1] = 0.5*(v1 + v0)
    {
        __half2 h01 = __floats2half2_rn(0.5f*(v0.x+vp.x), 0.5f*(v0.y+vp.y));
        __half2 h23 = __floats2half2_rn(0.5f*(v0.z+vp.z), 0.5f*(v0.w+vp.w));
        uint2 u; u.x = *(uint32_t*)&h01; u.y = *(uint32_t*)&h23;
        *(uint2*)(mh + (size_t)r0 * CC + tid * 4) = u;
    }
    {
        __half2 h01 = __floats2half2_rn(0.5f*(v1.x+v0.x), 0.5f*(v1.y+v0.y));
        __half2 h23 = __floats2half2_rn(0.5f*(v1.z+v0.z), 0.5f*(v1.w+v0.w));
        uint2 u; u.x = *(uint32_t*)&h01; u.y = *(uint32_t*)&h23;
        *(uint2*)(mh + (size_t)(r0 + 1) * CC + tid * 4) = u;
    }
}

// ---------------- LayerNorm (single, fp16 out) -----------------------
__global__ void ln_kernel(const float* __restrict__ x,
                          const float* __restrict__ g1, const float* __restrict__ b1,
                          f16* __restrict__ oh)
{
    __shared__ float sh[8];
    int row = blockIdx.x;
    int tid = threadIdx.x;
    float4 v = *(const float4*)(x + (size_t)row * CC + tid * 4);
    float mean = block_sum_256(v.x + v.y + v.z + v.w, sh) * (1.f / CC);
    float dx = v.x - mean, dy = v.y - mean, dz = v.z - mean, dw = v.w - mean;
    float var = block_sum_256(dx*dx + dy*dy + dz*dz + dw*dw, sh) * (1.f / CC);
    float rstd = rsqrtf(var + 1e-5f);
    float4 gv = *(const float4*)(g1 + tid * 4);
    float4 bv = *(const float4*)(b1 + tid * 4);
    __half2 h01 = __floats2half2_rn(dx * rstd * gv.x + bv.x, dy * rstd * gv.y + bv.y);
    __half2 h23 = __floats2half2_rn(dz * rstd * gv.z + bv.z, dw * rstd * gv.w + bv.w);
    uint2 u; u.x = *(uint32_t*)&h01; u.y = *(uint32_t*)&h23;
    *(uint2*)(oh + (size_t)row * CC + tid * 4) = u;
}

// ---------------- weight transpose (fp16 hi only) ---------------------
__global__ void transpose_split(const float* __restrict__ w, int R, int S, int ldout,
                                f16* __restrict__ th)
{
    __shared__ float t[32][33];
    int s0 = blockIdx.x * 32, r0 = blockIdx.y * 32;
    int tx = threadIdx.x, ty = threadIdx.y;   // (16,16)
#pragma unroll
    for (int i = ty; i < 32; i += 16) {
        float2 v = make_float2(0.f, 0.f);
        if (r0 + i < R) v = *(const float2*)(w + (size_t)(r0 + i) * S + s0 + tx * 2);
        t[i][tx*2] = v.x; t[i][tx*2+1] = v.y;
    }
    __syncthreads();
#pragma unroll
    for (int i = ty; i < 32; i += 16) {
        float a = t[tx*2][i], b = t[tx*2+1][i];
        size_t o = (size_t)(s0 + i) * ldout + r0 + tx * 2;
        __half2 hh = __floats2half2_rn(a, b);
        *(__half2*)(th + o) = hh;
    }
}

__global__ void transpose_split3(const float* __restrict__ w0, const float* __restrict__ w1,
                                 const float* __restrict__ w2,
                                 int R, int S, int ldout, size_t zoff,
                                 f16* __restrict__ th)
{
    __shared__ float t[32][33];
    const float* w = (blockIdx.z == 0) ? w0 : (blockIdx.z == 1) ? w1 : w2;
    th += blockIdx.z * zoff;
    int s0 = blockIdx.x * 32, r0 = blockIdx.y * 32;
    int tx = threadIdx.x, ty = threadIdx.y;
#pragma unroll
    for (int i = ty; i < 32; i += 16) {
        float2 v = make_float2(0.f, 0.f);
        if (r0 + i < R) v = *(const float2*)(w + (size_t)(r0 + i) * S + s0 + tx * 2);
        t[i][tx*2] = v.x; t[i][tx*2+1] = v.y;
    }
    __syncthreads();
#pragma unroll
    for (int i = ty; i < 32; i += 16) {
        float a = t[tx*2][i], b = t[tx*2+1][i];
        size_t o = (size_t)(s0 + i) * ldout + r0 + tx * 2;
        __half2 hh = __floats2half2_rn(a, b);
        *(__half2*)(th + o) = hh;
    }
}

// ---------------- HMMA fp16 GEMM (R8-proven shapes, 1-pass) -----------
template<int BM, int BN, int WMS, int WNS, int S,
         bool BIAS, bool GELU, bool RES, bool OUTF32, bool OUTH>
__global__ void __launch_bounds__(256, 2)
mm_h(int M, int N, int K, int lda, int ldh,
     size_t az, size_t bz, size_t czf, size_t czh,
     const f16* __restrict__ Ah, const f16* __restrict__ Bh,
     float* __restrict__ C, f16* __restrict__ Ch,
     const float* __restrict__ bias, const float* __restrict__ res)
{
    constexpr int NTH = 256;
    constexpr int TMW = BM / WMS;
    constexpr int TNW = BN / WNS;
    constexpr int MT = TMW / 16;
    constexpr int NT = TNW / 8;
    constexpr int A_BYTES = BM * 128;
    constexpr int B_BYTES = BN * 128;
    constexpr int STAGE   = A_BYTES + B_BYTES;

    extern __shared__ char smem[];
    const uint32_t sb = smem_u32(smem);

    const int z = blockIdx.z;
    Ah += (size_t)z * az;
    Bh += (size_t)z * bz;
    if (OUTF32) C  += (size_t)z * czf;
    if (OUTH)   Ch += (size_t)z * czh;

    const int tid  = threadIdx.x;
    const int lane = tid & 31;
    const int warp = tid >> 5;
    const int wm   = warp / WNS;
    const int wn   = warp % WNS;
    const int brow = blockIdx.y * BM;
    const int bcol = blockIdx.x * BN;
    const int NK   = K >> 6;

    float acc[MT][NT][4];
#pragma unroll
    for (int i = 0; i < MT; i++)
#pragma unroll
        for (int j = 0; j < NT; j++)
#pragma unroll
            for (int e = 0; e < 4; e++) acc[i][j][e] = 0.f;

    auto load_stage = [&](int kc, int s) {
        uint32_t base = sb + s * STAGE;
#pragma unroll 2
        for (int i = tid; i < BM * 8; i += NTH) {
            int r = i >> 3, j = i & 7;
            size_t go = (size_t)(brow + r) * lda + (size_t)kc * 64 + j * 8;
            uint32_t sw = SWZ128((uint32_t)(r * 128 + j * 16));
            cp16(base + sw, Ah + go);
        }
#pragma unroll 2
        for (int i = tid; i < BN * 8; i += NTH) {
            int r = i >> 3, j = i & 7;
            size_t go = (size_t)(bcol + r) * K + (size_t)kc * 64 + j * 8;
            uint32_t sw = SWZ128((uint32_t)(r * 128 + j * 16));
            cp16(base + A_BYTES + sw, Bh + go);
        }
        CP_COMMIT();
    };

    const int npre = (S - 1 < NK) ? S - 1 : NK;
    for (int i = 0; i < npre; i++) load_stage(i, i);
    for (int i = npre; i < S - 1; i++) CP_COMMIT();

    for (int kc = 0; kc < NK; kc++) {
        asm volatile("cp.async.wait_group %0;" :: "n"(S - 2) : "memory");
        __syncthreads();
        if (kc + S - 1 < NK) load_stage(kc + S - 1, (kc + S - 1) % S);
        else                 CP_COMMIT();

        const uint32_t st = sb + (kc % S) * STAGE;
#pragma unroll
        for (int ks = 0; ks < 4; ks++) {
            uint32_t a_h[MT][4];
#pragma unroll
            for (int mt = 0; mt < MT; mt++) {
                int r = wm * TMW + mt * 16 + (lane & 15);
                uint32_t off = SWZ128((uint32_t)(r * 128 + ks * 32 + ((lane >> 4) << 4)));
                ldsm_x4(a_h[mt], st + off);
            }
            uint32_t b_h[NT][2];
#pragma unroll
            for (int p = 0; p < NT / 2; p++) {
                int r = wn * TNW + p * 16 + (lane & 7) + ((lane >> 4) << 3);
                uint32_t off = SWZ128((uint32_t)(r * 128 + ks * 32 + (((lane >> 3) & 1) << 4)));
                uint32_t t4[4];
                ldsm_x4(t4, st + A_BYTES + off);
                b_h[2*p][0] = t4[0]; b_h[2*p][1] = t4[1];
                b_h[2*p+1][0] = t4[2]; b_h[2*p+1][1] = t4[3];
            }
#pragma unroll
            for (int mt = 0; mt < MT; mt++)
#pragma unroll
                for (int nt = 0; nt < NT; nt++) mma16816(acc[mt][nt], a_h[mt], b_h[nt]);
        }
    }

    // ---- epilogue ----
#pragma unroll
    for (int mt = 0; mt < MT; mt++) {
#pragma unroll
        for (int nt = 0; nt < NT; nt++) {
            int r0 = brow + wm * TMW + mt * 16 + (lane >> 2);
            int cg = bcol + wn * TNW + nt * 8 + ((lane & 3) << 1);
#pragma unroll
            for (int h = 0; h < 2; h++) {
                int r = r0 + h * 8;
                float v0 = acc[mt][nt][2*h], v1 = acc[mt][nt][2*h+1];
                if (BIAS) { v0 += bias[cg]; v1 += bias[cg + 1]; }
                if (GELU) { v0 = gelu_tanh(v0); v1 = gelu_tanh(v1); }
                if (RES) {
                    float2 rv = *(const float2*)(res + (size_t)r * N + cg);
                    v0 += rv.x; v1 += rv.y;
                }
                if (OUTF32)
                    *(float2*)(C + (size_t)r * N + cg) = make_float2(v0, v1);
                if (OUTH) {
                    __half2 hh = __floats2half2_rn(v0, v1);
                    *(__half2*)(Ch + (size_t)r * ldh + cg) = hh;
                }
            }
        }
    }
    if (OUTH && ldh > N) {
        int pads = (ldh - N) >> 3;
        for (int i = tid; i < BM * pads; i += NTH) {
            int r = brow + i / pads;
            int c = N + (i % pads) * 8;
            uint4 zv = make_uint4(0, 0, 0, 0);
            *(uint4*)(Ch + (size_t)r * ldh + c) = zv;
        }
    }
}

// ---------------- segmented scan (8 channels/thread, uint4 I/O) ------
__global__ void scan_local(const f16* __restrict__ k, const f16* __restrict__ v,
                           const float* __restrict__ td, float* __restrict__ hloc)
{
    int idx = blockIdx.x * blockDim.x + threadIdx.x;   // < SEG*BB*(CC/8)
    int c8 = idx & (CC/8 - 1);
    int rest = idx >> 7;
    int b = rest & (BB - 1);
    int seg = rest >> 3;
    int c0 = c8 * 8;
    float4 t0 = *(const float4*)(td + c0);
    float4 t1 = *(const float4*)(td + c0 + 4);
    float d[8] = {expf(-expf(t0.x)), expf(-expf(t0.y)), expf(-expf(t0.z)), expf(-expf(t0.w)),
                  expf(-expf(t1.x)), expf(-expf(t1.y)), expf(-expf(t1.z)), expf(-expf(t1.w))};
    float h[8] = {0.f,0.f,0.f,0.f,0.f,0.f,0.f,0.f};
    size_t base = ((size_t)(b * TT + seg * LSEG)) * CC + c0;
#pragma unroll 4
    for (int i = 0; i < LSEG; i++) {
        uint4 ku = *(const uint4*)(k + base);
        uint4 vu = *(const uint4*)(v + base);
        const __half2* kh = (const __half2*)&ku;
        const __half2* vh = (const __half2*)&vu;
#pragma unroll
        for (int j = 0; j < 4; j++) {
            float2 kf = __half22float2(kh[j]);
            float2 vf = __half22float2(vh[j]);
            h[2*j]   = d[2*j]   * h[2*j]   + kf.x * vf.x;
            h[2*j+1] = d[2*j+1] * h[2*j+1] + kf.y * vf.y;
        }
        base += CC;
    }
    int o = seg * BC + b * CC + c0;
    *(float4*)(hloc + o)     = make_float4(h[0], h[1], h[2], h[3]);
    *(float4*)(hloc + o + 4) = make_float4(h[4], h[5], h[6], h[7]);
}

__global__ void scan_combine(const float* __restrict__ hloc, const float* __restrict__ h0,
                             const float* __restrict__ td, float* __restrict__ hin,
                             float* __restrict__ out, long out_size)
{
    int rem = blockIdx.x * blockDim.x + threadIdx.x;   // < BC
    int c = rem & (CC - 1);
    float e = expf(td[c]);
    float dL = expf(-(float)LSEG * e);
    float h = h0[rem];
#pragma unroll
    for (int s = 0; s < SEG; s++) {
        hin[s * BC + rem] = h;
        h = dL * h + hloc[s * BC + rem];
    }
    if (out_size >= (long)MM * CC + BC)
        out[(size_t)MM * CC + rem] = h;
}

__global__ void scan_apply(const f16* __restrict__ k, const f16* __restrict__ v,
                           const f16* __restrict__ q, const float* __restrict__ td,
                           const float* __restrict__ hin, f16* __restrict__ yh)
{
    int idx = blockIdx.x * blockDim.x + threadIdx.x;
    int c8 = idx & (CC/8 - 1);
    int rest = idx >> 7;
    int b = rest & (BB - 1);
    int seg = rest >> 3;
    int c0 = c8 * 8;
    float4 t0 = *(const float4*)(td + c0);
    float4 t1 = *(const float4*)(td + c0 + 4);
    float d[8] = {expf(-expf(t0.x)), expf(-expf(t0.y)), expf(-expf(t0.z)), expf(-expf(t0.w)),
                  expf(-expf(t1.x)), expf(-expf(t1.y)), expf(-expf(t1.z)), expf(-expf(t1.w))};
    int ho = seg * BC + b * CC + c0;
    float4 h03 = *(const float4*)(hin + ho);
    float4 h47 = *(const float4*)(hin + ho + 4);
    float h[8] = {h03.x, h03.y, h03.z, h03.w, h47.x, h47.y, h47.z, h47.w};
    size_t base = ((size_t)(b * TT + seg * LSEG)) * CC + c0;
#pragma unroll 4
    for (int i = 0; i < LSEG; i++) {
        uint4 ku = *(const uint4*)(k + base);
        uint4 vu = *(const uint4*)(v + base);
        uint4 qu = *(const uint4*)(q + base);
        const __half2* kh = (const __half2*)&ku;
        const __half2* vh = (const __half2*)&vu;
        const __half2* qh = (const __half2*)&qu;
        uint4 yo;
        uint32_t* yp = (uint32_t*)&yo;
#pragma unroll
        for (int j = 0; j < 4; j++) {
            float2 kf = __half22float2(kh[j]);
            float2 vf = __half22float2(vh[j]);
            float2 qf = __half22float2(qh[j]);
            h[2*j]   = d[2*j]   * h[2*j]   + kf.x * vf.x;
            h[2*j+1] = d[2*j+1] * h[2*j+1] + kf.y * vf.y;
            __half2 yv = __floats2half2_rn(h[2*j]   * sigmoid_fast(qf.x),
                                           h[2*j+1] * sigmoid_fast(qf.y));
            yp[j] = *(uint32_t*)&yv;
        }
        *(uint4*)(yh + base) = yo;
        base += CC;
    }
}

// ---------------- launch ----------------------------------------------
#define SMEMSZ(BM, BN, S) ((S) * (((BM) + (BN)) * 128))

extern "C" void kernel_launch(void* const* d_in, const int* in_sizes, int n_in,
                              void* d_out, int out_size)
{
    const float* x     = (const float*)d_in[0];
    const float* h0    = (const float*)d_in[1];
    const float* ln1_g = (const float*)d_in[2];
    const float* ln1_b = (const float*)d_in[3];
    const float* tm_g  = (const float*)d_in[4];
    const float* tm_b  = (const float*)d_in[5];
    const float* qu    = (const float*)d_in[6];
    const float* qv    = (const float*)d_in[7];
    const float* ku    = (const float*)d_in[8];
    const float* kvw   = (const float*)d_in[9];
    const float* vu    = (const float*)d_in[10];
    const float* vvw   = (const float*)d_in[11];
    const float* td    = (const float*)d_in[12];
    const float* out_w = (const float*)d_in[13];
    const float* out_b = (const float*)d_in[14];
    const float* ln2_g = (const float*)d_in[15];
    const float* ln2_b = (const float*)d_in[16];
    const float* w1    = (const float*)d_in[17];
    const float* b1    = (const float*)d_in[18];
    const float* w2    = (const float*)d_in[19];
    const float* b2    = (const float*)d_in[20];
    const float* adw   = (const float*)d_in[21];
    const float* adb   = (const float*)d_in[22];
    const float* auw   = (const float*)d_in[23];
    const float* aub   = (const float*)d_in[24];
    float* out = (float*)d_out;

    void* p;
#define SYM(var, sym) cudaGetSymbolAddress(&p, sym); auto* var = (decltype(&sym[0]))p
    SYM(x1, g_x1);  SYM(x2, g_x2);
    SYM(hlc, g_hloc); SYM(hin, g_hin);
    SYM(mixh, g_mix_h);
    SYM(qkvrh, g_qkvr_h);
    SYM(qkv,  g_qkv);
    SYM(ysh, g_ys_h);
    SYM(h2h, g_h2_h);
    SYM(ffh, g_ff_h);
    SYM(x2h, g_x2h);
    SYM(adh, g_ad_h);
    SYM(uTh, g_uT_h);
    SYM(vTh, g_vT_h);
    SYM(owTh, g_owT_h);
    SYM(w1Th, g_w1T_h);
    SYM(w2Th, g_w2T_h);
    SYM(adwTh, g_adwT_h);
    SYM(auwTh, g_auwT_h);
#undef SYM
    f16* qf = qkv;
    f16* kf = qkv + (size_t)MM * CC;
    f16* vf = qkv + (size_t)2 * MM * CC;

    // variants: <BM, BN, WM, WN, STAGES, BIAS, GELU, RES, OUTF32, OUTH>
    auto mm_down = mm_h<128, 64,  4, 2, 3, false, false, false, false, true >;
    auto mm_up   = mm_h<128, 128, 2, 4, 2, false, false, false, false, true >;
    auto mm_oprj = mm_h<128, 128, 2, 4, 3, true,  false, true,  true,  false>;
    auto mm_ffn1 = mm_h<128, 128, 2, 4, 3, true,  true,  false, false, true >;
    auto mm_ffn2 = mm_h<128, 128, 2, 4, 3, true,  false, true,  true,  true >;
    auto mm_add  = mm_h<64,  32,  4, 2, 3, true,  true,  false, false, true >;  // BM=64: grid 256
    auto mm_adu  = mm_h<128, 128, 2, 4, 2, true,  false, true,  true,  false>;
    cudaFuncSetAttribute(mm_down, cudaFuncAttributeMaxDynamicSharedMemorySize, SMEMSZ(128,64,3));
    cudaFuncSetAttribute(mm_up,   cudaFuncAttributeMaxDynamicSharedMemorySize, SMEMSZ(128,128,2));
    cudaFuncSetAttribute(mm_oprj, cudaFuncAttributeMaxDynamicSharedMemorySize, SMEMSZ(128,128,3));
    cudaFuncSetAttribute(mm_ffn1, cudaFuncAttributeMaxDynamicSharedMemorySize, SMEMSZ(128,128,3));
    cudaFuncSetAttribute(mm_ffn2, cudaFuncAttributeMaxDynamicSharedMemorySize, SMEMSZ(128,128,3));
    cudaFuncSetAttribute(mm_add,  cudaFuncAttributeMaxDynamicSharedMemorySize, SMEMSZ(64,32,3));
    cudaFuncSetAttribute(mm_adu,  cudaFuncAttributeMaxDynamicSharedMemorySize, SMEMSZ(128,128,2));

    dim3 tb(16, 16);
    const bool dual = g_ss.ok;
    cudaStream_t s2 = dual ? g_ss.s : (cudaStream_t)0;
    cudaEvent_t eFork = g_ss.ev[0], eJoinT = g_ss.ev[1];

    // ---- main: qkv weight transposes ----
    transpose_split3<<<dim3(RR/32, CC/32, 3), tb>>>(qu, ku, vu, CC, RR, CC,
                                                    (size_t)RR*CC, uTh);

    // ---- fork: late-needed weight transposes on side stream ----
    if (dual) {
        cudaEventRecord(eFork, 0);
        cudaStreamWaitEvent(s2, eFork, 0);
    }
    transpose_split<<<dim3(CC/32,  CC/32), tb, 0, s2>>>(out_w, CC, CC, CC, owTh);
    transpose_split<<<dim3(FFD/32, CC/32), tb, 0, s2>>>(w1,  CC, FFD, CC,  w1Th);
    transpose_split<<<dim3(CC/32,  FFD/32),tb, 0, s2>>>(w2,  FFD, CC, FFD, w2Th);
    transpose_split<<<dim3(ARR/32, CC/32), tb, 0, s2>>>(adw, CC, ARR, CC,  adwTh);
    transpose_split<<<dim3(CC/32,  64/32), tb, 0, s2>>>(auw, ARR, CC, 64,  auwTh);
    if (dual) cudaEventRecord(eJoinT, s2);

    // ---- main chain ----
    transpose_split3<<<dim3(CC/32, RR/32, 3), tb>>>(qv, kvw, vvw, RR, CC, RR,
                                                    (size_t)CC*RR, vTh);
    ln1_mix_kernel<<<MM/2, 256>>>(x, ln1_g, ln1_b, tm_g, tm_b, mixh);

    // fused low-rank down-projections (1-pass): [M,1024]@[192,1024]^T
    mm_down<<<dim3(3, MM/128), 256, SMEMSZ(128,64,3)>>>(
        MM, 3*RR, CC, CC, 3*RR, 0, 0, 0, 0,
        mixh, uTh, nullptr, qkvrh, nullptr, nullptr);

    // batched up-projections (1-pass, z = q,k,v) -> fp16 qkv
    mm_up<<<dim3(CC/128, MM/128, 3), 256, SMEMSZ(128,128,2)>>>(
        MM, CC, RR, 3*RR, CC, RR, (size_t)CC*RR, 0, (size_t)MM*CC,
        qkvrh, vTh, nullptr, qkv, nullptr, nullptr);

    // segmented scan (vectorized, 8 ch/thread) -> ys fp16
    scan_local  <<<SEG*BB*(CC/8)/256, 256>>>(kf, vf, td, hlc);
    scan_combine<<<BC/256, 256>>>(hlc, h0, td, hin, out, (long)out_size);
    scan_apply  <<<SEG*BB*(CC/8)/256, 256>>>(kf, vf, qf, td, hin, ysh);

    // ---- join: side-stream transposes must be done before their consumers
    if (dual) cudaStreamWaitEvent(0, eJoinT, 0);

    // out-proj (1-pass) + bias + residual(x) -> x1 fp32
    mm_oprj<<<dim3(CC/128, MM/128), 256, SMEMSZ(128,128,3)>>>(
        MM, CC, CC, CC, 0, 0, 0, 0, 0,
        ysh, owTh, x1, nullptr, out_b, x);

    // h2 = LN2(x1) -> fp16
    ln_kernel<<<MM, 256>>>(x1, ln2_g, ln2_b, h2h);

    // FFN (1-pass)
    mm_ffn1<<<dim3(FFD/128, MM/128), 256, SMEMSZ(128,128,3)>>>(
        MM, FFD, CC, CC, FFD, 0, 0, 0, 0,
        h2h, w1Th, nullptr, ffh, b1, nullptr);
    mm_ffn2<<<dim3(CC/128, MM/128), 256, SMEMSZ(128,128,3)>>>(
        MM, CC, FFD, FFD, CC, 0, 0, 0, 0,
        ffh, w2Th, x2, x2h, b2, x1);

    // adapter: down (1-pass, BM=64 for full-chip grid) then up + residual
    mm_add<<<dim3(1, MM/64), 256, SMEMSZ(64,32,3)>>>(
        MM, ARR, CC, CC, 64, 0, 0, 0, 0,
        x2h, adwTh, nullptr, adh, adb, nullptr);
    mm_adu<<<dim3(CC/128, MM/128), 256, SMEMSZ(128,128,2)>>>(
        MM, CC, 64, 64, 0, 0, 0, 0, 0,
        adh, auwTh, out, nullptr, aub, x2);
}

// round 17
// speedup vs baseline: 1.0475x; 1.0159x over previous
#include <cuda_runtime.h>
#include <cuda_fp16.h>
#include <math.h>
#include <stdint.h>

// ---------------- problem constants (fixed shapes) ----------------
#define BB   8
#define TT   2048
#define CC   1024
#define RR   64
#define ARR  32
#define FFD  4096
#define MM   (BB*TT)        // 16384 rows
#define SEG  128
#define LSEG (TT/SEG)       // 16
#define BC   (BB*CC)        // 8192 channels

typedef __half f16;

// ---------------- side stream (created at load, NOT in kernel_launch) ---
struct SideStream {
    cudaStream_t s = 0;
    cudaEvent_t ev[2] = {};
    bool ok = false;
    SideStream() {
        ok = (cudaStreamCreateWithFlags(&s, cudaStreamNonBlocking) == cudaSuccess);
        for (int i = 0; i < 2 && ok; i++)
            ok = (cudaEventCreateWithFlags(&ev[i], cudaEventDisableTiming) == cudaSuccess);
    }
};
static SideStream g_ss;   // constructed before harness checkpoints

// ---------------- scratch (static device globals; no allocs) ------
__device__ __align__(256) float g_hloc[SEG*BC];
__device__ __align__(256) float g_hin [SEG*BC];

// fp16 activation buffers
__device__ __align__(256) f16 g_mix_h[MM*CC];
__device__ __align__(256) f16 g_qkvr_h[MM*3*RR];                 // [M,192] q|k|v
__device__ __align__(256) f16 g_qkv[(size_t)3*MM*CC];            // q,k,v fp16
__device__ __align__(256) f16 g_ys_h[MM*CC];
__device__ __align__(256) f16 g_x1h[MM*CC];                      // x + attn (fp16)
__device__ __align__(256) f16 g_h2_h[MM*CC];
__device__ __align__(256) f16 g_ff_h[(size_t)MM*FFD];
__device__ __align__(256) f16 g_x2h[MM*CC];                      // after FFN (fp16)
__device__ __align__(256) f16 g_ad_h[MM*64];                     // K padded 32->64

// fp16 transposed weights ([N,K] K-major)
__device__ __align__(256) f16 g_uT_h[3*RR*CC];                   // qu|ku|vu [192,1024]
__device__ __align__(256) f16 g_vT_h[3*CC*RR];                   // qv|kv|vv 3x[1024,64]
__device__ __align__(256) f16 g_owT_h[CC*CC];
__device__ __align__(256) f16 g_w1T_h[(size_t)FFD*CC];
__device__ __align__(256) f16 g_w2T_h[(size_t)CC*FFD];
__device__ __align__(256) f16 g_adwT_h[ARR*CC];
__device__ __align__(256) f16 g_auwT_h[CC*64];                   // K padded 32->64

// ---------------- PTX helpers ---------------------------------------
__device__ __forceinline__ uint32_t smem_u32(const void* p) {
    uint32_t a;
    asm("{ .reg .u64 t; cvta.to.shared.u64 t, %1; cvt.u32.u64 %0, t; }" : "=r"(a) : "l"(p));
    return a;
}
#define SWZ128(b) ((b) ^ (((b) >> 3) & 0x70))

__device__ __forceinline__ void cp16(uint32_t dst, const void* src) {
    asm volatile("cp.async.cg.shared.global [%0], [%1], 16;" :: "r"(dst), "l"(src));
}
#define CP_COMMIT()  asm volatile("cp.async.commit_group;" ::: "memory")

__device__ __forceinline__ void ldsm_x4(uint32_t* r, uint32_t addr) {
    asm volatile("ldmatrix.sync.aligned.m8n8.x4.shared.b16 {%0,%1,%2,%3}, [%4];"
                 : "=r"(r[0]), "=r"(r[1]), "=r"(r[2]), "=r"(r[3]) : "r"(addr));
}
__device__ __forceinline__ void mma16816(float* d, const uint32_t* a, const uint32_t* b) {
    asm volatile("mma.sync.aligned.m16n8k16.row.col.f32.f16.f16.f32 "
                 "{%0,%1,%2,%3}, {%4,%5,%6,%7}, {%8,%9}, {%0,%1,%2,%3};"
                 : "+f"(d[0]), "+f"(d[1]), "+f"(d[2]), "+f"(d[3])
                 : "r"(a[0]), "r"(a[1]), "r"(a[2]), "r"(a[3]), "r"(b[0]), "r"(b[1]));
}
__device__ __forceinline__ float tanh_fast(float x) {
    float y;
    asm("tanh.approx.f32 %0, %1;" : "=f"(y) : "f"(x));
    return y;
}

// ---------------- misc helpers --------------------------------------
__device__ __forceinline__ float gelu_tanh(float x) {
    float x3 = x * x * x;
    return 0.5f * x * (1.f + tanh_fast(0.7978845608028654f * (x + 0.044715f * x3)));
}
__device__ __forceinline__ float sigmoid_fast(float x) {
    return 0.5f + 0.5f * tanh_fast(0.5f * x);
}
__device__ __forceinline__ float block_sum_256(float val, float* sh) {
    int lane = threadIdx.x & 31;
#pragma unroll
    for (int o = 16; o > 0; o >>= 1) val += __shfl_xor_sync(0xffffffffu, val, o);
    if (lane == 0) sh[threadIdx.x >> 5] = val;
    __syncthreads();
    float r = (lane < 8) ? sh[lane] : 0.f;
#pragma unroll
    for (int o = 4; o > 0; o >>= 1) r += __shfl_xor_sync(0xffffffffu, r, o);
    r = __shfl_sync(0xffffffffu, r, 0);
    __syncthreads();
    return r;
}

// double-LN of one row's float4 slice (two chained LayerNorms)
__device__ __forceinline__ float4 ln2x(float4 v,
                                       const float* __restrict__ g1, const float* __restrict__ b1,
                                       const float* __restrict__ g2, const float* __restrict__ b2,
                                       int tid, float* sh)
{
#pragma unroll
    for (int pass = 0; pass < 2; pass++) {
        const float* gg = pass ? g2 : g1;
        const float* bb = pass ? b2 : b1;
        float mean = block_sum_256(v.x + v.y + v.z + v.w, sh) * (1.f / CC);
        float dx = v.x - mean, dy = v.y - mean, dz = v.z - mean, dw = v.w - mean;
        float var = block_sum_256(dx*dx + dy*dy + dz*dz + dw*dw, sh) * (1.f / CC);
        float rstd = rsqrtf(var + 1e-5f);
        float4 gv = *(const float4*)(gg + tid * 4);
        float4 bv = *(const float4*)(bb + tid * 4);
        v.x = dx * rstd * gv.x + bv.x;
        v.y = dy * rstd * gv.y + bv.y;
        v.z = dz * rstd * gv.z + bv.z;
        v.w = dw * rstd * gv.w + bv.w;
    }
    return v;
}

// ---- fused double-LN + token-shift mix, 2 rows/block (shares LN(r0)) ----
__global__ void ln1_mix_kernel(const float* __restrict__ x,
                               const float* __restrict__ g1, const float* __restrict__ b1,
                               const float* __restrict__ g2, const float* __restrict__ b2,
                               f16* __restrict__ mh)
{
    __shared__ float sh[8];
    int r0 = blockIdx.x * 2;
    int tid = threadIdx.x;
    int t0 = r0 & (TT - 1);

    float4 vp = make_float4(0.f, 0.f, 0.f, 0.f);
    if (t0 > 0) {
        vp = *(const float4*)(x + (size_t)(r0 - 1) * CC + tid * 4);
        vp = ln2x(vp, g1, b1, g2, b2, tid, sh);
    }
    float4 v0 = *(const float4*)(x + (size_t)r0 * CC + tid * 4);
    v0 = ln2x(v0, g1, b1, g2, b2, tid, sh);
    float4 v1 = *(const float4*)(x + (size_t)(r0 + 1) * CC + tid * 4);
    v1 = ln2x(v1, g1, b1, g2, b2, tid, sh);

    {
        __half2 h01 = __floats2half2_rn(0.5f*(v0.x+vp.x), 0.5f*(v0.y+vp.y));
        __half2 h23 = __floats2half2_rn(0.5f*(v0.z+vp.z), 0.5f*(v0.w+vp.w));
        uint2 u; u.x = *(uint32_t*)&h01; u.y = *(uint32_t*)&h23;
        *(uint2*)(mh + (size_t)r0 * CC + tid * 4) = u;
    }
    {
        __half2 h01 = __floats2half2_rn(0.5f*(v1.x+v0.x), 0.5f*(v1.y+v0.y));
        __half2 h23 = __floats2half2_rn(0.5f*(v1.z+v0.z), 0.5f*(v1.w+v0.w));
        uint2 u; u.x = *(uint32_t*)&h01; u.y = *(uint32_t*)&h23;
        *(uint2*)(mh + (size_t)(r0 + 1) * CC + tid * 4) = u;
    }
}

// ---------------- LayerNorm (fp16 in, fp16 out) -----------------------
__global__ void ln_kernel_h(const f16* __restrict__ x,
                            const float* __restrict__ g1, const float* __restrict__ b1,
                            f16* __restrict__ oh)
{
    __shared__ float sh[8];
    int row = blockIdx.x;
    int tid = threadIdx.x;
    uint2 u = *(const uint2*)(x + (size_t)row * CC + tid * 4);
    float2 p0 = __half22float2(*(__half2*)&u.x);
    float2 p1 = __half22float2(*(__half2*)&u.y);
    float4 v = make_float4(p0.x, p0.y, p1.x, p1.y);
    float mean = block_sum_256(v.x + v.y + v.z + v.w, sh) * (1.f / CC);
    float dx = v.x - mean, dy = v.y - mean, dz = v.z - mean, dw = v.w - mean;
    float var = block_sum_256(dx*dx + dy*dy + dz*dz + dw*dw, sh) * (1.f / CC);
    float rstd = rsqrtf(var + 1e-5f);
    float4 gv = *(const float4*)(g1 + tid * 4);
    float4 bv = *(const float4*)(b1 + tid * 4);
    __half2 h01 = __floats2half2_rn(dx * rstd * gv.x + bv.x, dy * rstd * gv.y + bv.y);
    __half2 h23 = __floats2half2_rn(dz * rstd * gv.z + bv.z, dw * rstd * gv.w + bv.w);
    uint2 o; o.x = *(uint32_t*)&h01; o.y = *(uint32_t*)&h23;
    *(uint2*)(oh + (size_t)row * CC + tid * 4) = o;
}

// ---------------- weight transpose (fp16 hi only) ---------------------
__global__ void transpose_split(const float* __restrict__ w, int R, int S, int ldout,
                                f16* __restrict__ th)
{
    __shared__ float t[32][33];
    int s0 = blockIdx.x * 32, r0 = blockIdx.y * 32;
    int tx = threadIdx.x, ty = threadIdx.y;   // (16,16)
#pragma unroll
    for (int i = ty; i < 32; i += 16) {
        float2 v = make_float2(0.f, 0.f);
        if (r0 + i < R) v = *(const float2*)(w + (size_t)(r0 + i) * S + s0 + tx * 2);
        t[i][tx*2] = v.x; t[i][tx*2+1] = v.y;
    }
    __syncthreads();
#pragma unroll
    for (int i = ty; i < 32; i += 16) {
        float a = t[tx*2][i], b = t[tx*2+1][i];
        size_t o = (size_t)(s0 + i) * ldout + r0 + tx * 2;
        __half2 hh = __floats2half2_rn(a, b);
        *(__half2*)(th + o) = hh;
    }
}

__global__ void transpose_split3(const float* __restrict__ w0, const float* __restrict__ w1,
                                 const float* __restrict__ w2,
                                 int R, int S, int ldout, size_t zoff,
                                 f16* __restrict__ th)
{
    __shared__ float t[32][33];
    const float* w = (blockIdx.z == 0) ? w0 : (blockIdx.z == 1) ? w1 : w2;
    th += blockIdx.z * zoff;
    int s0 = blockIdx.x * 32, r0 = blockIdx.y * 32;
    int tx = threadIdx.x, ty = threadIdx.y;
#pragma unroll
    for (int i = ty; i < 32; i += 16) {
        float2 v = make_float2(0.f, 0.f);
        if (r0 + i < R) v = *(const float2*)(w + (size_t)(r0 + i) * S + s0 + tx * 2);
        t[i][tx*2] = v.x; t[i][tx*2+1] = v.y;
    }
    __syncthreads();
#pragma unroll
    for (int i = ty; i < 32; i += 16) {
        float a = t[tx*2][i], b = t[tx*2+1][i];
        size_t o = (size_t)(s0 + i) * ldout + r0 + tx * 2;
        __half2 hh = __floats2half2_rn(a, b);
        *(__half2*)(th + o) = hh;
    }
}

// ---------------- HMMA fp16 GEMM (1-pass, fp16/fp32 residual) ---------
template<int BM, int BN, int WMS, int WNS, int S,
         bool BIAS, bool GELU, bool RES, bool RESH, bool OUTF32, bool OUTH>
__global__ void __launch_bounds__(256, 2)
mm_h(int M, int N, int K, int lda, int ldh,
     size_t az, size_t bz, size_t czf, size_t czh,
     const f16* __restrict__ Ah, const f16* __restrict__ Bh,
     float* __restrict__ C, f16* __restrict__ Ch,
     const float* __restrict__ bias,
     const float* __restrict__ resf, const f16* __restrict__ resh)
{
    constexpr int NTH = 256;
    constexpr int TMW = BM / WMS;
    constexpr int TNW = BN / WNS;
    constexpr int MT = TMW / 16;
    constexpr int NT = TNW / 8;
    constexpr int A_BYTES = BM * 128;
    constexpr int B_BYTES = BN * 128;
    constexpr int STAGE   = A_BYTES + B_BYTES;

    extern __shared__ char smem[];
    const uint32_t sb = smem_u32(smem);

    const int z = blockIdx.z;
    Ah += (size_t)z * az;
    Bh += (size_t)z * bz;
    if (OUTF32) C  += (size_t)z * czf;
    if (OUTH)   Ch += (size_t)z * czh;

    const int tid  = threadIdx.x;
    const int lane = tid & 31;
    const int warp = tid >> 5;
    const int wm   = warp / WNS;
    const int wn   = warp % WNS;
    const int brow = blockIdx.y * BM;
    const int bcol = blockIdx.x * BN;
    const int NK   = K >> 6;

    float acc[MT][NT][4];
#pragma unroll
    for (int i = 0; i < MT; i++)
#pragma unroll
        for (int j = 0; j < NT; j++)
#pragma unroll
            for (int e = 0; e < 4; e++) acc[i][j][e] = 0.f;

    auto load_stage = [&](int kc, int s) {
        uint32_t base = sb + s * STAGE;
#pragma unroll 2
        for (int i = tid; i < BM * 8; i += NTH) {
            int r = i >> 3, j = i & 7;
            size_t go = (size_t)(brow + r) * lda + (size_t)kc * 64 + j * 8;
            uint32_t sw = SWZ128((uint32_t)(r * 128 + j * 16));
            cp16(base + sw, Ah + go);
        }
#pragma unroll 2
        for (int i = tid; i < BN * 8; i += NTH) {
            int r = i >> 3, j = i & 7;
            size_t go = (size_t)(bcol + r) * K + (size_t)kc * 64 + j * 8;
            uint32_t sw = SWZ128((uint32_t)(r * 128 + j * 16));
            cp16(base + A_BYTES + sw, Bh + go);
        }
        CP_COMMIT();
    };

    const int npre = (S - 1 < NK) ? S - 1 : NK;
    for (int i = 0; i < npre; i++) load_stage(i, i);
    for (int i = npre; i < S - 1; i++) CP_COMMIT();

    for (int kc = 0; kc < NK; kc++) {
        asm volatile("cp.async.wait_group %0;" :: "n"(S - 2) : "memory");
        __syncthreads();
        if (kc + S - 1 < NK) load_stage(kc + S - 1, (kc + S - 1) % S);
        else                 CP_COMMIT();

        const uint32_t st = sb + (kc % S) * STAGE;
#pragma unroll
        for (int ks = 0; ks < 4; ks++) {
            uint32_t a_h[MT][4];
#pragma unroll
            for (int mt = 0; mt < MT; mt++) {
                int r = wm * TMW + mt * 16 + (lane & 15);
                uint32_t off = SWZ128((uint32_t)(r * 128 + ks * 32 + ((lane >> 4) << 4)));
                ldsm_x4(a_h[mt], st + off);
            }
            uint32_t b_h[NT][2];
#pragma unroll
            for (int p = 0; p < NT / 2; p++) {
                int r = wn * TNW + p * 16 + (lane & 7) + ((lane >> 4) << 3);
                uint32_t off = SWZ128((uint32_t)(r * 128 + ks * 32 + (((lane >> 3) & 1) << 4)));
                uint32_t t4[4];
                ldsm_x4(t4, st + A_BYTES + off);
                b_h[2*p][0] = t4[0]; b_h[2*p][1] = t4[1];
                b_h[2*p+1][0] = t4[2]; b_h[2*p+1][1] = t4[3];
            }
#pragma unroll
            for (int mt = 0; mt < MT; mt++)
#pragma unroll
                for (int nt = 0; nt < NT; nt++) mma16816(acc[mt][nt], a_h[mt], b_h[nt]);
        }
    }

    // ---- epilogue ----
#pragma unroll
    for (int mt = 0; mt < MT; mt++) {
#pragma unroll
        for (int nt = 0; nt < NT; nt++) {
            int r0 = brow + wm * TMW + mt * 16 + (lane >> 2);
            int cg = bcol + wn * TNW + nt * 8 + ((lane & 3) << 1);
#pragma unroll
            for (int h = 0; h < 2; h++) {
                int r = r0 + h * 8;
                float v0 = acc[mt][nt][2*h], v1 = acc[mt][nt][2*h+1];
                if (BIAS) { v0 += bias[cg]; v1 += bias[cg + 1]; }
                if (GELU) { v0 = gelu_tanh(v0); v1 = gelu_tanh(v1); }
                if (RES) {
                    if (RESH) {
                        __half2 rv = *(const __half2*)(resh + (size_t)r * N + cg);
                        float2 rf = __half22float2(rv);
                        v0 += rf.x; v1 += rf.y;
                    } else {
                        float2 rv = *(const float2*)(resf + (size_t)r * N + cg);
                        v0 += rv.x; v1 += rv.y;
                    }
                }
                if (OUTF32)
                    *(float2*)(C + (size_t)r * N + cg) = make_float2(v0, v1);
                if (OUTH) {
                    __half2 hh = __floats2half2_rn(v0, v1);
                    *(__half2*)(Ch + (size_t)r * ldh + cg) = hh;
                }
            }
        }
    }
    if (OUTH && ldh > N) {
        int pads = (ldh - N) >> 3;
        for (int i = tid; i < BM * pads; i += NTH) {
            int r = brow + i / pads;
            int c = N + (i % pads) * 8;
            uint4 zv = make_uint4(0, 0, 0, 0);
            *(uint4*)(Ch + (size_t)r * ldh + c) = zv;
        }
    }
}

// ---------------- segmented scan (8 channels/thread, uint4 I/O) ------
__global__ void scan_local(const f16* __restrict__ k, const f16* __restrict__ v,
                           const float* __restrict__ td, float* __restrict__ hloc)
{
    int idx = blockIdx.x * blockDim.x + threadIdx.x;   // < SEG*BB*(CC/8)
    int c8 = idx & (CC/8 - 1);
    int rest = idx >> 7;
    int b = rest & (BB - 1);
    int seg = rest >> 3;
    int c0 = c8 * 8;
    float4 t0 = *(const float4*)(td + c0);
    float4 t1 = *(const float4*)(td + c0 + 4);
    float d[8] = {expf(-expf(t0.x)), expf(-expf(t0.y)), expf(-expf(t0.z)), expf(-expf(t0.w)),
                  expf(-expf(t1.x)), expf(-expf(t1.y)), expf(-expf(t1.z)), expf(-expf(t1.w))};
    float h[8] = {0.f,0.f,0.f,0.f,0.f,0.f,0.f,0.f};
    size_t base = ((size_t)(b * TT + seg * LSEG)) * CC + c0;
#pragma unroll 4
    for (int i = 0; i < LSEG; i++) {
        uint4 ku = *(const uint4*)(k + base);
        uint4 vu = *(const uint4*)(v + base);
        const __half2* kh = (const __half2*)&ku;
        const __half2* vh = (const __half2*)&vu;
#pragma unroll
        for (int j = 0; j < 4; j++) {
            float2 kf = __half22float2(kh[j]);
            float2 vf = __half22float2(vh[j]);
            h[2*j]   = d[2*j]   * h[2*j]   + kf.x * vf.x;
            h[2*j+1] = d[2*j+1] * h[2*j+1] + kf.y * vf.y;
        }
        base += CC;
    }
    int o = seg * BC + b * CC + c0;
    *(float4*)(hloc + o)     = make_float4(h[0], h[1], h[2], h[3]);
    *(float4*)(hloc + o + 4) = make_float4(h[4], h[5], h[6], h[7]);
}

__global__ void scan_combine(const float* __restrict__ hloc, const float* __restrict__ h0,
                             const float* __restrict__ td, float* __restrict__ hin,
                             float* __restrict__ out, long out_size)
{
    int rem = blockIdx.x * blockDim.x + threadIdx.x;   // < BC
    int c = rem & (CC - 1);
    float e = expf(td[c]);
    float dL = expf(-(float)LSEG * e);
    float h = h0[rem];
#pragma unroll
    for (int s = 0; s < SEG; s++) {
        hin[s * BC + rem] = h;
        h = dL * h + hloc[s * BC + rem];
    }
    if (out_size >= (long)MM * CC + BC)
        out[(size_t)MM * CC + rem] = h;
}

__global__ void scan_apply(const f16* __restrict__ k, const f16* __restrict__ v,
                           const f16* __restrict__ q, const float* __restrict__ td,
                           const float* __restrict__ hin, f16* __restrict__ yh)
{
    int idx = blockIdx.x * blockDim.x + threadIdx.x;
    int c8 = idx & (CC/8 - 1);
    int rest = idx >> 7;
    int b = rest & (BB - 1);
    int seg = rest >> 3;
    int c0 = c8 * 8;
    float4 t0 = *(const float4*)(td + c0);
    float4 t1 = *(const float4*)(td + c0 + 4);
    float d[8] = {expf(-expf(t0.x)), expf(-expf(t0.y)), expf(-expf(t0.z)), expf(-expf(t0.w)),
                  expf(-expf(t1.x)), expf(-expf(t1.y)), expf(-expf(t1.z)), expf(-expf(t1.w))};
    int ho = seg * BC + b * CC + c0;
    float4 h03 = *(const float4*)(hin + ho);
    float4 h47 = *(const float4*)(hin + ho + 4);
    float h[8] = {h03.x, h03.y, h03.z, h03.w, h47.x, h47.y, h47.z, h47.w};
    size_t base = ((size_t)(b * TT + seg * LSEG)) * CC + c0;
#pragma unroll 4
    for (int i = 0; i < LSEG; i++) {
        uint4 ku = *(const uint4*)(k + base);
        uint4 vu = *(const uint4*)(v + base);
        uint4 qu = *(const uint4*)(q + base);
        const __half2* kh = (const __half2*)&ku;
        const __half2* vh = (const __half2*)&vu;
        const __half2* qh = (const __half2*)&qu;
        uint4 yo;
        uint32_t* yp = (uint32_t*)&yo;
#pragma unroll
        for (int j = 0; j < 4; j++) {
            float2 kf = __half22float2(kh[j]);
            float2 vf = __half22float2(vh[j]);
            float2 qf = __half22float2(qh[j]);
            h[2*j]   = d[2*j]   * h[2*j]   + kf.x * vf.x;
            h[2*j+1] = d[2*j+1] * h[2*j+1] + kf.y * vf.y;
            __half2 yv = __floats2half2_rn(h[2*j]   * sigmoid_fast(qf.x),
                                           h[2*j+1] * sigmoid_fast(qf.y));
            yp[j] = *(uint32_t*)&yv;
        }
        *(uint4*)(yh + base) = yo;
        base += CC;
    }
}

// ---------------- launch ----------------------------------------------
#define SMEMSZ(BM, BN, S) ((S) * (((BM) + (BN)) * 128))

extern "C" void kernel_launch(void* const* d_in, const int* in_sizes, int n_in,
                              void* d_out, int out_size)
{
    const float* x     = (const float*)d_in[0];
    const float* h0    = (const float*)d_in[1];
    const float* ln1_g = (const float*)d_in[2];
    const float* ln1_b = (const float*)d_in[3];
    const float* tm_g  = (const float*)d_in[4];
    const float* tm_b  = (const float*)d_in[5];
    const float* qu    = (const float*)d_in[6];
    const float* qv    = (const float*)d_in[7];
    const float* ku    = (const float*)d_in[8];
    const float* kvw   = (const float*)d_in[9];
    const float* vu    = (const float*)d_in[10];
    const float* vvw   = (const float*)d_in[11];
    const float* td    = (const float*)d_in[12];
    const float* out_w = (const float*)d_in[13];
    const float* out_b = (const float*)d_in[14];
    const float* ln2_g = (const float*)d_in[15];
    const float* ln2_b = (const float*)d_in[16];
    const float* w1    = (const float*)d_in[17];
    const float* b1    = (const float*)d_in[18];
    const float* w2    = (const float*)d_in[19];
    const float* b2    = (const float*)d_in[20];
    const float* adw   = (const float*)d_in[21];
    const float* adb   = (const float*)d_in[22];
    const float* auw   = (const float*)d_in[23];
    const float* aub   = (const float*)d_in[24];
    float* out = (float*)d_out;

    void* p;
#define SYM(var, sym) cudaGetSymbolAddress(&p, sym); auto* var = (decltype(&sym[0]))p
    SYM(hlc, g_hloc); SYM(hin, g_hin);
    SYM(mixh, g_mix_h);
    SYM(qkvrh, g_qkvr_h);
    SYM(qkv,  g_qkv);
    SYM(ysh, g_ys_h);
    SYM(x1h, g_x1h);
    SYM(h2h, g_h2_h);
    SYM(ffh, g_ff_h);
    SYM(x2h, g_x2h);
    SYM(adh, g_ad_h);
    SYM(uTh, g_uT_h);
    SYM(vTh, g_vT_h);
    SYM(owTh, g_owT_h);
    SYM(w1Th, g_w1T_h);
    SYM(w2Th, g_w2T_h);
    SYM(adwTh, g_adwT_h);
    SYM(auwTh, g_auwT_h);
#undef SYM
    f16* qf = qkv;
    f16* kf = qkv + (size_t)MM * CC;
    f16* vf = qkv + (size_t)2 * MM * CC;

    // variants: <BM, BN, WM, WN, S, BIAS, GELU, RES, RESH, OUTF32, OUTH>
    auto mm_down = mm_h<128, 64,  4, 2, 3, false, false, false, false, false, true >;
    auto mm_up   = mm_h<128, 128, 2, 4, 2, false, false, false, false, false, true >;
    auto mm_oprj = mm_h<128, 128, 2, 4, 3, true,  false, true,  false, false, true >;
    auto mm_ffn1 = mm_h<128, 128, 2, 4, 3, true,  true,  false, false, false, true >;
    auto mm_ffn2 = mm_h<128, 128, 2, 4, 3, true,  false, true,  true,  false, true >;
    auto mm_add  = mm_h<64,  32,  4, 2, 3, true,  true,  false, false, false, true >;
    auto mm_adu  = mm_h<128, 128, 2, 4, 2, true,  false, true,  true,  true,  false>;
    cudaFuncSetAttribute(mm_down, cudaFuncAttributeMaxDynamicSharedMemorySize, SMEMSZ(128,64,3));
    cudaFuncSetAttribute(mm_up,   cudaFuncAttributeMaxDynamicSharedMemorySize, SMEMSZ(128,128,2));
    cudaFuncSetAttribute(mm_oprj, cudaFuncAttributeMaxDynamicSharedMemorySize, SMEMSZ(128,128,3));
    cudaFuncSetAttribute(mm_ffn1, cudaFuncAttributeMaxDynamicSharedMemorySize, SMEMSZ(128,128,3));
    cudaFuncSetAttribute(mm_ffn2, cudaFuncAttributeMaxDynamicSharedMemorySize, SMEMSZ(128,128,3));
    cudaFuncSetAttribute(mm_add,  cudaFuncAttributeMaxDynamicSharedMemorySize, SMEMSZ(64,32,3));
    cudaFuncSetAttribute(mm_adu,  cudaFuncAttributeMaxDynamicSharedMemorySize, SMEMSZ(128,128,2));

    dim3 tb(16, 16);
    const bool dual = g_ss.ok;
    cudaStream_t s2 = dual ? g_ss.s : (cudaStream_t)0;
    cudaEvent_t eFork = g_ss.ev[0], eJoinT = g_ss.ev[1];

    // ---- main: qkv weight transposes ----
    transpose_split3<<<dim3(RR/32, CC/32, 3), tb>>>(qu, ku, vu, CC, RR, CC,
                                                    (size_t)RR*CC, uTh);

    // ---- fork: late-needed weight transposes on side stream ----
    if (dual) {
        cudaEventRecord(eFork, 0);
        cudaStreamWaitEvent(s2, eFork, 0);
    }
    transpose_split<<<dim3(CC/32,  CC/32), tb, 0, s2>>>(out_w, CC, CC, CC, owTh);
    transpose_split<<<dim3(FFD/32, CC/32), tb, 0, s2>>>(w1,  CC, FFD, CC,  w1Th);
    transpose_split<<<dim3(CC/32,  FFD/32),tb, 0, s2>>>(w2,  FFD, CC, FFD, w2Th);
    transpose_split<<<dim3(ARR/32, CC/32), tb, 0, s2>>>(adw, CC, ARR, CC,  adwTh);
    transpose_split<<<dim3(CC/32,  64/32), tb, 0, s2>>>(auw, ARR, CC, 64,  auwTh);
    if (dual) cudaEventRecord(eJoinT, s2);

    // ---- main chain ----
    transpose_split3<<<dim3(CC/32, RR/32, 3), tb>>>(qv, kvw, vvw, RR, CC, RR,
                                                    (size_t)CC*RR, vTh);
    ln1_mix_kernel<<<MM/2, 256>>>(x, ln1_g, ln1_b, tm_g, tm_b, mixh);

    // fused low-rank down-projections (1-pass): [M,1024]@[192,1024]^T
    mm_down<<<dim3(3, MM/128), 256, SMEMSZ(128,64,3)>>>(
        MM, 3*RR, CC, CC, 3*RR, 0, 0, 0, 0,
        mixh, uTh, nullptr, qkvrh, nullptr, nullptr, nullptr);

    // batched up-projections (1-pass, z = q,k,v) -> fp16 qkv
    mm_up<<<dim3(CC/128, MM/128, 3), 256, SMEMSZ(128,128,2)>>>(
        MM, CC, RR, 3*RR, CC, RR, (size_t)CC*RR, 0, (size_t)MM*CC,
        qkvrh, vTh, nullptr, qkv, nullptr, nullptr, nullptr);

    // segmented scan (vectorized, 8 ch/thread) -> ys fp16
    scan_local  <<<SEG*BB*(CC/8)/256, 256>>>(kf, vf, td, hlc);
    scan_combine<<<BC/256, 256>>>(hlc, h0, td, hin, out, (long)out_size);
    scan_apply  <<<SEG*BB*(CC/8)/256, 256>>>(kf, vf, qf, td, hin, ysh);

    // ---- join: side-stream transposes must be done before their consumers
    if (dual) cudaStreamWaitEvent(0, eJoinT, 0);

    // out-proj + bias + residual(x, fp32) -> x1 fp16
    mm_oprj<<<dim3(CC/128, MM/128), 256, SMEMSZ(128,128,3)>>>(
        MM, CC, CC, CC, CC, 0, 0, 0, 0,
        ysh, owTh, nullptr, x1h, out_b, x, nullptr);

    // h2 = LN2(x1h) -> fp16
    ln_kernel_h<<<MM, 256>>>(x1h, ln2_g, ln2_b, h2h);

    // FFN (1-pass); ffn2 residual = x1h (fp16), out -> x2 fp16
    mm_ffn1<<<dim3(FFD/128, MM/128), 256, SMEMSZ(128,128,3)>>>(
        MM, FFD, CC, CC, FFD, 0, 0, 0, 0,
        h2h, w1Th, nullptr, ffh, b1, nullptr, nullptr);
    mm_ffn2<<<dim3(CC/128, MM/128), 256, SMEMSZ(128,128,3)>>>(
        MM, CC, FFD, FFD, CC, 0, 0, 0, 0,
        ffh, w2Th, nullptr, x2h, b2, nullptr, x1h);

    // adapter: down (BM=64 full-chip grid) then up + residual(x2h) -> out fp32
    mm_add<<<dim3(1, MM/64), 256, SMEMSZ(64,32,3)>>>(
        MM, ARR, CC, CC, 64, 0, 0, 0, 0,
        x2h, adwTh, nullptr, adh, adb, nullptr, nullptr);
    mm_adu<<<dim3(CC/128, MM/128), 256, SMEMSZ(128,128,2)>>>(
        MM, CC, 64, 64, 0, 0, 0, 0, 0,
        adh, auwTh, out, nullptr, aub, nullptr, x2h);
}